// round 11
// baseline (speedup 1.0000x reference)
#include <cuda_runtime.h>
#include <cuda_bf16.h>
#include <math.h>
#include <stdint.h>

#define NN 4096
#define NW 128
#define H 4
#define F1 128
#define F2 32
#define HN (H * NN)
#define IN_F 512
#define HID1 64
#define OUT_F 16
#define LRELU 0.2f
#define BN_EPS 1e-5f

// ---------------- scratch ----------------
__device__ float         g_h1[NN * 512];
__device__ float         g_x2[NN * HID1];
__device__ float         g_h2[NN * 128];
__device__ float         g_x3[NN * 128];
__device__ float         g_z4[NN * OUT_F];
__device__ float         g_sc1[6 * HN];
__device__ float         g_sc2[6 * HN];
__device__ unsigned      g_mask[NN * NW];
__device__ float         g_mean[64], g_rstd[64];
__device__ float         g_bnpart[32 * 2 * 64];
__device__ float         g_part[2 * NN * 512];   // K-split partial accumulators
__device__ float         g_dp[2 * HN];           // K-split partial denominators
__device__ __nv_bfloat16 g_h1th[512 * NN];
__device__ __nv_bfloat16 g_h1tl[512 * NN];
__device__ __nv_bfloat16 g_h2th[128 * NN];
__device__ __nv_bfloat16 g_h2tl[128 * NN];
__device__ __nv_bfloat16 g_ah[NN * 512];
__device__ __nv_bfloat16 g_al[NN * 512];
__device__ __nv_bfloat16 g_wth[512 * 512];
__device__ __nv_bfloat16 g_wtl[512 * 512];
__device__ __nv_bfloat16 g_lw1th[HID1 * 512];
__device__ __nv_bfloat16 g_lw1tl[HID1 * 512];
__device__ __nv_bfloat16 g_w2th[128 * HID1];
__device__ __nv_bfloat16 g_w2tl[128 * HID1];

// ================= helpers =================
__device__ __forceinline__ uint32_t smem_u32(const void* p) {
    uint32_t a;
    asm("{ .reg .u64 t; cvta.to.shared.u64 t, %1; cvt.u32.u64 %0, t; }" : "=r"(a) : "l"(p));
    return a;
}
__device__ __forceinline__ void cp16(uint32_t dst, const void* src) {
    asm volatile("cp.async.cg.shared.global [%0], [%1], 16;" :: "r"(dst), "l"(src));
}
__device__ __forceinline__ void cp8(uint32_t dst, const void* src) {
    asm volatile("cp.async.ca.shared.global [%0], [%1], 8;" :: "r"(dst), "l"(src));
}
#define CP_COMMIT() asm volatile("cp.async.commit_group;" ::: "memory")
#define CP_WAIT1()  asm volatile("cp.async.wait_group 1;" ::: "memory")

__device__ __forceinline__ void mma16816(float* c,
    uint32_t a0, uint32_t a1, uint32_t a2, uint32_t a3, uint32_t b0, uint32_t b1) {
    asm volatile(
        "mma.sync.aligned.m16n8k16.row.col.f32.bf16.bf16.f32 "
        "{%0,%1,%2,%3}, {%4,%5,%6,%7}, {%8,%9}, {%0,%1,%2,%3};"
        : "+f"(c[0]), "+f"(c[1]), "+f"(c[2]), "+f"(c[3])
        : "r"(a0), "r"(a1), "r"(a2), "r"(a3), "r"(b0), "r"(b1));
}
__device__ __forceinline__ void ldsm4(uint32_t& r0, uint32_t& r1, uint32_t& r2, uint32_t& r3,
                                      uint32_t addr) {
    asm volatile("ldmatrix.sync.aligned.m8n8.x4.shared.b16 {%0,%1,%2,%3}, [%4];"
                 : "=r"(r0), "=r"(r1), "=r"(r2), "=r"(r3) : "r"(addr));
}
__device__ __forceinline__ float wmax(float E, float e, float Ev, float e2, unsigned bit) {
    float v = fmaxf(E * Ev, e * e2);
    return bit ? v : 0.f;
}
__device__ __forceinline__ void packtr(float a, float b, uint32_t& hi, uint32_t& lo) {
    uint32_t au = __float_as_uint(a), bu = __float_as_uint(b);
    hi = __byte_perm(au, bu, 0x7632);
    float la = a - __uint_as_float(au & 0xFFFF0000u);
    float lb = b - __uint_as_float(bu & 0xFFFF0000u);
    __nv_bfloat162 l2 = __floats2bfloat162_rn(la, lb);
    lo = *(uint32_t*)&l2;
}

// ---------------- adjacency -> bitmask ----------------
__global__ void k_pack_mask(const int* __restrict__ adj) {
    int gw   = (blockIdx.x * blockDim.x + threadIdx.x) >> 5;
    int lane = threadIdx.x & 31;
    int v = adj[(size_t)gw * 32 + lane];
    unsigned m = __ballot_sync(0xffffffffu, v > 0);
    if (lane == 0) g_mask[gw] = m;
}

// ---------------- elementwise fp32 -> bf16 hi/lo split ----------------
__global__ void k_split_bf16(const float* __restrict__ in,
                             __nv_bfloat16* __restrict__ oh,
                             __nv_bfloat16* __restrict__ ol) {
    int idx = blockIdx.x * blockDim.x + threadIdx.x;
    float4 v = ((const float4*)in)[idx];
    __nv_bfloat162 h0 = __floats2bfloat162_rn(v.x, v.y);
    __nv_bfloat162 h1 = __floats2bfloat162_rn(v.z, v.w);
    __nv_bfloat162 l0 = __floats2bfloat162_rn(v.x - __bfloat162float(h0.x),
                                              v.y - __bfloat162float(h0.y));
    __nv_bfloat162 l1 = __floats2bfloat162_rn(v.z - __bfloat162float(h1.x),
                                              v.w - __bfloat162float(h1.y));
    ((__nv_bfloat162*)oh)[idx * 2] = h0;
    ((__nv_bfloat162*)oh)[idx * 2 + 1] = h1;
    ((__nv_bfloat162*)ol)[idx * 2] = l0;
    ((__nv_bfloat162*)ol)[idx * 2 + 1] = l1;
}

// ---------------- transpose fp32 [R,C] -> bf16 hi/lo [C,R] ----------------
__global__ void k_transpose_split(const float* __restrict__ in,
                                  __nv_bfloat16* __restrict__ oh,
                                  __nv_bfloat16* __restrict__ ol, int R, int C) {
    __shared__ float tile[32][33];
    int r0 = blockIdx.x * 32, c0 = blockIdx.y * 32;
    int tx = threadIdx.x, ty = threadIdx.y;
#pragma unroll
    for (int q = 0; q < 4; q++)
        tile[ty * 4 + q][tx] = in[(size_t)(r0 + ty * 4 + q) * C + c0 + tx];
    __syncthreads();
#pragma unroll
    for (int q = 0; q < 4; q++) {
        float v = tile[tx][ty * 4 + q];
        __nv_bfloat16 hi = __float2bfloat16(v);
        float lo = v - __bfloat162float(hi);
        size_t o = (size_t)(c0 + ty * 4 + q) * R + r0 + tx;
        oh[o] = hi;
        ol[o] = __float2bfloat16(lo);
    }
}

// ================ split-bf16 HMMA GEMM, 3-stage pipeline ================
template <int BN, int NWARP>
__device__ __forceinline__ void gemm_load(int t, int m0, int n0, int c, int buf,
                                          uint32_t sb, int K,
                                          const __nv_bfloat16* Ah, const __nv_bfloat16* Al,
                                          const __nv_bfloat16* Bh, const __nv_bfloat16* Bl) {
    constexpr int AB = 16384;
    constexpr int BB = BN * 128;
    constexpr int STAGE = 2 * AB + 2 * BB;
    uint32_t base = sb + buf * STAGE;
#pragma unroll
    for (int idx = t; idx < 1024; idx += NWARP * 32) {
        int m = idx >> 3, q = idx & 7;
        uint32_t off = base + (uint32_t)(m * 128 + ((q ^ (m & 7)) << 4));
        size_t src = (size_t)(m0 + m) * K + c * 64 + q * 8;
        cp16(off, Ah + src);
        cp16(off + AB, Al + src);
    }
#pragma unroll
    for (int idx = t; idx < BN * 8; idx += NWARP * 32) {
        int n = idx >> 3, q = idx & 7;
        uint32_t off = base + 2 * AB + (uint32_t)(n * 128 + ((q ^ (n & 7)) << 4));
        size_t src = (size_t)(n0 + n) * K + c * 64 + q * 8;
        cp16(off, Bh + src);
        cp16(off + BB, Bl + src);
    }
}

template <int BN, int NWARP>
__global__ __launch_bounds__(NWARP * 32) void k_gemm_hmma(
    const __nv_bfloat16* __restrict__ Ah, const __nv_bfloat16* __restrict__ Al,
    const __nv_bfloat16* __restrict__ Bh, const __nv_bfloat16* __restrict__ Bl,
    const float* __restrict__ bias, float* __restrict__ C, int K, int Ntot) {
    constexpr int AB = 16384;
    constexpr int BB = BN * 128;
    constexpr int STAGE = 2 * AB + 2 * BB;
    extern __shared__ char sm[];
    uint32_t sb = smem_u32(sm);
    int t = threadIdx.x, wid = t >> 5, lane = t & 31;
    int m0 = blockIdx.x * 128, n0 = blockIdx.y * BN;
    int wm = (wid & 3) * 32, wn = (wid >> 2) * 32;
    int g = lane >> 2, tig = lane & 3;
    int nc = K >> 6;

    int arow = (lane & 7) + ((lane >> 3) & 1) * 8;
    int ahalf = lane >> 4;
    int brow = ((lane >> 4) << 3) + (lane & 7);
    int bhalf = (lane >> 3) & 1;

    float acc[2][4][4];
#pragma unroll
    for (int mt = 0; mt < 2; mt++)
#pragma unroll
        for (int nt = 0; nt < 4; nt++)
#pragma unroll
            for (int q = 0; q < 4; q++) acc[mt][nt][q] = 0.f;

    gemm_load<BN, NWARP>(t, m0, n0, 0, 0, sb, K, Ah, Al, Bh, Bl);
    CP_COMMIT();
    if (nc > 1) gemm_load<BN, NWARP>(t, m0, n0, 1, 1, sb, K, Ah, Al, Bh, Bl);
    CP_COMMIT();

    for (int c = 0; c < nc; c++) {
        int buf = c % 3;
        CP_WAIT1();
        __syncthreads();
        if (c + 2 < nc)
            gemm_load<BN, NWARP>(t, m0, n0, c + 2, (c + 2) % 3, sb, K, Ah, Al, Bh, Bl);
        CP_COMMIT();
        uint32_t base = sb + buf * STAGE;
#pragma unroll
        for (int ks = 0; ks < 4; ks++) {
            uint32_t ahf[2][4], alf[2][4], bhf[2][4], blf[2][4];
#pragma unroll
            for (int mt = 0; mt < 2; mt++) {
                int r = wm + mt * 16 + arow;
                int slot = 2 * ks + ahalf;
                uint32_t ad = base + (uint32_t)(r * 128 + ((slot ^ (r & 7)) << 4));
                ldsm4(ahf[mt][0], ahf[mt][1], ahf[mt][2], ahf[mt][3], ad);
                ldsm4(alf[mt][0], alf[mt][1], alf[mt][2], alf[mt][3], ad + AB);
            }
#pragma unroll
            for (int np = 0; np < 2; np++) {
                int r = wn + np * 16 + brow;
                int slot = 2 * ks + bhalf;
                uint32_t bd = base + 2 * AB + (uint32_t)(r * 128 + ((slot ^ (r & 7)) << 4));
                ldsm4(bhf[np][0], bhf[np][1], bhf[np][2], bhf[np][3], bd);
                ldsm4(blf[np][0], blf[np][1], blf[np][2], blf[np][3], bd + BB);
            }
#pragma unroll
            for (int mt = 0; mt < 2; mt++)
#pragma unroll
                for (int nt = 0; nt < 4; nt++) {
                    int np = nt >> 1, sel = (nt & 1) * 2;
                    mma16816(acc[mt][nt], ahf[mt][0], ahf[mt][1], ahf[mt][2], ahf[mt][3],
                             bhf[np][sel], bhf[np][sel + 1]);
                }
#pragma unroll
            for (int mt = 0; mt < 2; mt++)
#pragma unroll
                for (int nt = 0; nt < 4; nt++) {
                    int np = nt >> 1, sel = (nt & 1) * 2;
                    mma16816(acc[mt][nt], ahf[mt][0], ahf[mt][1], ahf[mt][2], ahf[mt][3],
                             blf[np][sel], blf[np][sel + 1]);
                }
#pragma unroll
            for (int mt = 0; mt < 2; mt++)
#pragma unroll
                for (int nt = 0; nt < 4; nt++) {
                    int np = nt >> 1, sel = (nt & 1) * 2;
                    mma16816(acc[mt][nt], alf[mt][0], alf[mt][1], alf[mt][2], alf[mt][3],
                             bhf[np][sel], bhf[np][sel + 1]);
                }
        }
    }
#pragma unroll
    for (int mt = 0; mt < 2; mt++)
#pragma unroll
        for (int nt = 0; nt < 4; nt++) {
            int row = m0 + wm + mt * 16 + g;
            int col = n0 + wn + nt * 8 + tig * 2;
            float bv0 = bias ? bias[col] : 0.f;
            float bv1 = bias ? bias[col + 1] : 0.f;
            float2 v0 = make_float2(acc[mt][nt][0] + bv0, acc[mt][nt][1] + bv1);
            float2 v1 = make_float2(acc[mt][nt][2] + bv0, acc[mt][nt][3] + bv1);
            *(float2*)&C[(size_t)row * Ntot + col] = v0;
            *(float2*)&C[(size_t)(row + 8) * Ntot + col] = v1;
        }
}

// ---------------- fp32 GEMM for lin2 ----------------
template <int BM, int BN, int BK, int TM, int TN>
__global__ void k_gemm_bias(const float* __restrict__ A, const float* __restrict__ B,
                            const float* __restrict__ bias, float* __restrict__ C,
                            int M, int Nn, int K) {
    constexpr int THREADS = (BM / TM) * (BN / TN);
    __shared__ float As[BM][BK + 1];
    __shared__ float Bs[BK][BN + 1];
    int tid = threadIdx.x;
    int rm = tid / (BN / TN);
    int rn = tid % (BN / TN);
    int m0 = blockIdx.y * BM, n0 = blockIdx.x * BN;
    float acc[TM][TN];
#pragma unroll
    for (int m = 0; m < TM; m++)
#pragma unroll
        for (int n = 0; n < TN; n++) acc[m][n] = 0.f;

    for (int k0 = 0; k0 < K; k0 += BK) {
        for (int idx = tid; idx < BM * BK; idx += THREADS) {
            int r = idx / BK, c = idx % BK;
            As[r][c] = A[(size_t)(m0 + r) * K + k0 + c];
        }
        for (int idx = tid; idx < BK * BN; idx += THREADS) {
            int r = idx / BN, c = idx % BN;
            Bs[r][c] = B[(size_t)(k0 + r) * Nn + n0 + c];
        }
        __syncthreads();
#pragma unroll
        for (int kk = 0; kk < BK; kk++) {
            float a[TM], b[TN];
#pragma unroll
            for (int m = 0; m < TM; m++) a[m] = As[rm * TM + m][kk];
#pragma unroll
            for (int n = 0; n < TN; n++) b[n] = Bs[kk][rn * TN + n];
#pragma unroll
            for (int m = 0; m < TM; m++)
#pragma unroll
                for (int n = 0; n < TN; n++) acc[m][n] = fmaf(a[m], b[n], acc[m][n]);
        }
        __syncthreads();
    }
#pragma unroll
    for (int m = 0; m < TM; m++) {
        int row = m0 + rm * TM + m;
#pragma unroll
        for (int n = 0; n < TN; n++) {
            int col = n0 + rn * TN + n;
            float v = acc[m][n];
            if (bias) v += bias[col];
            C[(size_t)row * Nn + col] = v;
        }
    }
}

// ---------------- per-node scores + precomputed exps ----------------
template <int F>
__global__ void k_attn_scores(const float* __restrict__ hfeat,
                              const float* __restrict__ a_src,
                              const float* __restrict__ a_dst,
                              float* __restrict__ sc) {
    int n = blockIdx.x * (blockDim.x >> 5) + (threadIdx.x >> 5);
    int lane = threadIdx.x & 31;
    if (n >= NN) return;
    const float* row = hfeat + (size_t)n * (H * F);
#pragma unroll
    for (int h = 0; h < H; h++) {
        float ss = 0.f, sd = 0.f;
        for (int k = lane; k < F; k += 32) {
            float v = row[h * F + k];
            ss = fmaf(v, a_src[h * F + k], ss);
            sd = fmaf(v, a_dst[h * F + k], sd);
        }
#pragma unroll
        for (int o = 16; o; o >>= 1) {
            ss += __shfl_xor_sync(0xffffffffu, ss, o);
            sd += __shfl_xor_sync(0xffffffffu, sd, o);
        }
        if (lane == 0) {
            int idx = h * NN + n;
            sc[0 * HN + idx] = ss;
            sc[1 * HN + idx] = expf(ss);
            sc[2 * HN + idx] = expf(LRELU * ss);
            sc[3 * HN + idx] = sd;
            sc[4 * HN + idx] = expf(sd);
            sc[5 * HN + idx] = expf(LRELU * sd);
        }
    }
}

// ================ GAT aggregation: K-split, 8 warps x (16 rows, full F) ================
template <int F>
__device__ __forceinline__ void load_chunk(int t, int head, int i0, int c, int buf,
                                           char* BtB, unsigned* mk, float* edb,
                                           const __nv_bfloat16* hTh,
                                           const __nv_bfloat16* hTl,
                                           const float* sc) {
    constexpr int BT = F * 128;
    char* dsthi = BtB + buf * 2 * BT;
    char* dstlo = dsthi + BT;
    for (int idx = t; idx < F * 8; idx += 256) {
        int f = idx >> 3, q = idx & 7;
        uint32_t off = (uint32_t)(f * 128 + (((q ^ (f & 7)) << 4)));
        size_t src = (size_t)(head * F + f) * NN + c * 64 + q * 8;
        cp16(smem_u32(dsthi + off), hTh + src);
        cp16(smem_u32(dstlo + off), hTl + src);
    }
    if (t < 128) cp8(smem_u32(mk + buf * 256 + t * 2), &g_mask[(size_t)(i0 + t) * NW + c * 2]);
    if (t < 32) {
        int a = t >> 4, q = t & 15;
        cp16(smem_u32(edb + buf * 128 + a * 64 + q * 4),
             &sc[(size_t)(4 + a) * HN + head * NN + c * 64 + q * 4]);
    }
}

template <int F>
__global__ __launch_bounds__(256) void k_gat_hmma(const __nv_bfloat16* __restrict__ hTh,
                                                  const __nv_bfloat16* __restrict__ hTl,
                                                  const float* __restrict__ sc,
                                                  float* __restrict__ part,
                                                  float* __restrict__ dp) {
    constexpr int BT = F * 128;
    constexpr int MPF = F / 16;
    extern __shared__ char smem[];
    char* BtB = smem;                               // [3][2*BT]
    unsigned* mk = (unsigned*)(smem + 6 * BT);      // [3][256]
    float* edb = (float*)(smem + 6 * BT + 3072);    // [3][128]

    int t = threadIdx.x, wid = t >> 5, lane = t & 31;
    int g = lane >> 2, tig = lane & 3;
    int head = blockIdx.y, i0 = blockIdx.x * 128;
    int z = blockIdx.z;
    int c0 = z * 32;
    uint32_t sb = smem_u32(smem);

    int r0 = wid * 16 + g, r1 = r0 + 8;
    const float* scb = sc + head * NN + i0;
    float E0 = scb[HN + r0], e0 = scb[2 * HN + r0];
    float E1 = scb[HN + r1], e1 = scb[2 * HN + r1];

    int flr = ((lane >> 4) & 1) * 8 + (lane & 7);
    int qb = (lane >> 3) & 1;
    int sxw = flr & 7;
    uint32_t fcol = (uint32_t)(flr * 128);

    float acc[2 * MPF][4];
#pragma unroll
    for (int nt = 0; nt < 2 * MPF; nt++)
#pragma unroll
        for (int q = 0; q < 4; q++) acc[nt][q] = 0.f;
    float d0 = 0.f, d1 = 0.f;

    load_chunk<F>(t, head, i0, c0, 0, BtB, mk, edb, hTh, hTl, sc);
    CP_COMMIT();
    load_chunk<F>(t, head, i0, c0 + 1, 1, BtB, mk, edb, hTh, hTl, sc);
    CP_COMMIT();

    for (int cc = 0; cc < 32; cc++) {
        int b = cc % 3;
        CP_WAIT1();
        __syncthreads();
        if (cc < 30)
            load_chunk<F>(t, head, i0, c0 + cc + 2, (cc + 2) % 3, BtB, mk, edb, hTh, hTl, sc);
        CP_COMMIT();
        unsigned* mkb = mk + b * 256;
        unsigned m0a = mkb[r0 * 2], m0b = mkb[r0 * 2 + 1];
        unsigned m1a = mkb[r1 * 2], m1b = mkb[r1 * 2 + 1];
        float* ed = edb + b * 128;
        uint32_t bufbase = sb + (uint32_t)(b * 2 * BT);
#pragma unroll
        for (int ks = 0; ks < 4; ks++) {
            int jb = ks * 16 + tig * 2;
            float2 EvL = *(float2*)&ed[jb];
            float2 EvH = *(float2*)&ed[jb + 8];
            float2 e2L = *(float2*)&ed[64 + jb];
            float2 e2H = *(float2*)&ed[64 + jb + 8];
            int bit = (ks & 1) * 16 + tig * 2;
            unsigned w0 = (ks < 2) ? m0a : m0b;
            unsigned w1 = (ks < 2) ? m1a : m1b;

            float a0 = wmax(E0, e0, EvL.x, e2L.x, (w0 >> bit) & 1u);
            float a1 = wmax(E0, e0, EvL.y, e2L.y, (w0 >> (bit + 1)) & 1u);
            float a2 = wmax(E0, e0, EvH.x, e2H.x, (w0 >> (bit + 8)) & 1u);
            float a3 = wmax(E0, e0, EvH.y, e2H.y, (w0 >> (bit + 9)) & 1u);
            float b0 = wmax(E1, e1, EvL.x, e2L.x, (w1 >> bit) & 1u);
            float b1 = wmax(E1, e1, EvL.y, e2L.y, (w1 >> (bit + 1)) & 1u);
            float b2 = wmax(E1, e1, EvH.x, e2H.x, (w1 >> (bit + 8)) & 1u);
            float b3 = wmax(E1, e1, EvH.y, e2H.y, (w1 >> (bit + 9)) & 1u);
            d0 += a0 + a1 + a2 + a3;
            d1 += b0 + b1 + b2 + b3;
            uint32_t Ahh[4], All[4];
            packtr(a0, a1, Ahh[0], All[0]);
            packtr(b0, b1, Ahh[1], All[1]);
            packtr(a2, a3, Ahh[2], All[2]);
            packtr(b2, b3, Ahh[3], All[3]);

            uint32_t swz = (uint32_t)((((2 * ks + qb) ^ sxw) << 4));
#pragma unroll
            for (int mp = 0; mp < MPF; mp++) {
                uint32_t ad = bufbase + fcol + (uint32_t)(mp * 2048) + swz;
                uint32_t bh0, bh1, bh2, bh3, bl0, bl1, bl2, bl3;
                ldsm4(bh0, bh1, bh2, bh3, ad);
                ldsm4(bl0, bl1, bl2, bl3, ad + BT);
                float* c0a = acc[2 * mp];
                float* c1a = acc[2 * mp + 1];
                mma16816(c0a, Ahh[0], Ahh[1], Ahh[2], Ahh[3], bh0, bh1);
                mma16816(c1a, Ahh[0], Ahh[1], Ahh[2], Ahh[3], bh2, bh3);
                mma16816(c0a, Ahh[0], Ahh[1], Ahh[2], Ahh[3], bl0, bl1);
                mma16816(c1a, Ahh[0], Ahh[1], Ahh[2], Ahh[3], bl2, bl3);
                mma16816(c0a, All[0], All[1], All[2], All[3], bh0, bh1);
                mma16816(c1a, All[0], All[1], All[2], All[3], bh2, bh3);
            }
        }
    }
    d0 += __shfl_xor_sync(0xffffffffu, d0, 1);
    d0 += __shfl_xor_sync(0xffffffffu, d0, 2);
    d1 += __shfl_xor_sync(0xffffffffu, d1, 1);
    d1 += __shfl_xor_sync(0xffffffffu, d1, 2);
    if (tig == 0) {
        dp[(size_t)z * HN + head * NN + i0 + r0] = d0;
        dp[(size_t)z * HN + head * NN + i0 + r1] = d1;
    }
    float* pz = part + (size_t)z * NN * (H * F);
#pragma unroll
    for (int nt = 0; nt < 2 * MPF; nt++) {
        int col = head * F + nt * 8 + tig * 2;
        *(float2*)&pz[(size_t)(i0 + r0) * (H * F) + col] = make_float2(acc[nt][0], acc[nt][1]);
        *(float2*)&pz[(size_t)(i0 + r1) * (H * F) + col] = make_float2(acc[nt][2], acc[nt][3]);
    }
}

// ---- combine K-split partials, normalize, optional bf16 split output ----
template <int F, bool SPLIT>
__global__ void k_gat_fin(const float* __restrict__ part, const float* __restrict__ dp,
                          float* __restrict__ out,
                          __nv_bfloat16* __restrict__ oh, __nv_bfloat16* __restrict__ ol) {
    constexpr int HF = H * F;
    int idx = blockIdx.x * blockDim.x + threadIdx.x;  // one float4
    int e0 = idx * 4;
    int row = e0 / HF, cc = e0 % HF, head = cc / F;
    float inv = 1.f / (dp[head * NN + row] + dp[HN + head * NN + row]);
    float4 p0 = ((const float4*)part)[idx];
    float4 p1 = ((const float4*)(part + (size_t)NN * HF))[idx];
    float v0 = (p0.x + p1.x) * inv, v1 = (p0.y + p1.y) * inv;
    float v2 = (p0.z + p1.z) * inv, v3 = (p0.w + p1.w) * inv;
    if (SPLIT) {
        __nv_bfloat162 h0 = __floats2bfloat162_rn(v0, v1);
        __nv_bfloat162 h1 = __floats2bfloat162_rn(v2, v3);
        __nv_bfloat162 l0 = __floats2bfloat162_rn(v0 - __bfloat162float(h0.x),
                                                  v1 - __bfloat162float(h0.y));
        __nv_bfloat162 l1 = __floats2bfloat162_rn(v2 - __bfloat162float(h1.x),
                                                  v3 - __bfloat162float(h1.y));
        ((__nv_bfloat162*)oh)[idx * 2] = h0;
        ((__nv_bfloat162*)oh)[idx * 2 + 1] = h1;
        ((__nv_bfloat162*)ol)[idx * 2] = l0;
        ((__nv_bfloat162*)ol)[idx * 2 + 1] = l1;
    } else {
        ((float4*)out)[idx] = make_float4(v0, v1, v2, v3);
    }
}

// ---------------- batchnorm: two-stage coalesced stats ----------------
template <int C>
__global__ void k_bn_part(const float* __restrict__ z, float* __restrict__ part) {
    constexpr int RL = 256 / C;
    int blk = blockIdx.x;
    int t = threadIdx.x;
    int col = t % C, rl = t / C;
    float s = 0.f, s2 = 0.f;
    for (int r = rl; r < 128; r += RL) {
        float v = z[(size_t)(blk * 128 + r) * C + col];
        s += v; s2 += v * v;
    }
    __shared__ float sh[256], sh2[256];
    sh[t] = s; sh2[t] = s2;
    __syncthreads();
    if (rl == 0) {
#pragma unroll
        for (int q = 1; q < RL; q++) { s += sh[q * C + col]; s2 += sh2[q * C + col]; }
        part[blk * 2 * C + col] = s;
        part[blk * 2 * C + C + col] = s2;
    }
}
template <int C>
__global__ void k_bn_fin(const float* __restrict__ part,
                         float* __restrict__ mean, float* __restrict__ rstd) {
    int c = threadIdx.x;
    if (c >= C) return;
    double s = 0.0, s2 = 0.0;
    for (int b = 0; b < 32; b++) { s += part[b * 2 * C + c]; s2 += part[b * 2 * C + C + c]; }
    double mu = s / NN;
    double var = s2 / NN - mu * mu;
    mean[c] = (float)mu;
    rstd[c] = rsqrtf((float)var + BN_EPS);
}

__global__ void k_bn_elu(const float* __restrict__ z, const float* __restrict__ mean,
                         const float* __restrict__ rstd, const float* __restrict__ gamma,
                         const float* __restrict__ beta, float* __restrict__ out, int C) {
    int idx = blockIdx.x * blockDim.x + threadIdx.x;
    int c = idx % C;
    float v = (z[idx] - mean[c]) * rstd[c] * gamma[c] + beta[c];
    out[idx] = v > 0.f ? v : (expf(v) - 1.f);
}

__global__ void k_bn_elu_split(const float* __restrict__ z, const float* __restrict__ mean,
                               const float* __restrict__ rstd, const float* __restrict__ gamma,
                               const float* __restrict__ beta,
                               __nv_bfloat16* __restrict__ oh, __nv_bfloat16* __restrict__ ol,
                               int C) {
    int idx = blockIdx.x * blockDim.x + threadIdx.x;
    int c = idx % C;
    float v = (z[idx] - mean[c]) * rstd[c] * gamma[c] + beta[c];
    v = v > 0.f ? v : (expf(v) - 1.f);
    __nv_bfloat16 hi = __float2bfloat16(v);
    oh[idx] = hi;
    ol[idx] = __float2bfloat16(v - __bfloat162float(hi));
}

// ---------------- launch ----------------
extern "C" void kernel_launch(void* const* d_in, const int* in_sizes, int n_in,
                              void* d_out, int out_size) {
    const float* x   = (const float*)d_in[0];
    const int*   adj = (const int*)d_in[1];
    const float* W1  = (const float*)d_in[2];
    const float* a1s = (const float*)d_in[3];
    const float* a1d = (const float*)d_in[4];
    const float* lw1 = (const float*)d_in[5];
    const float* lb1 = (const float*)d_in[6];
    const float* g1  = (const float*)d_in[7];
    const float* be1 = (const float*)d_in[8];
    const float* W2  = (const float*)d_in[9];
    const float* a2s = (const float*)d_in[10];
    const float* a2d = (const float*)d_in[11];
    const float* lw2 = (const float*)d_in[12];
    const float* lb2 = (const float*)d_in[13];
    const float* g2  = (const float*)d_in[14];
    const float* be2 = (const float*)d_in[15];
    float* out = (float*)d_out;

    float *h1, *x2, *h2, *x3, *z4, *sc1, *sc2, *mean, *rstd, *bnp, *part, *dp;
    __nv_bfloat16 *h1th, *h1tl, *h2th, *h2tl, *ah, *al, *wth, *wtl;
    __nv_bfloat16 *lw1th, *lw1tl, *w2th, *w2tl;
    cudaGetSymbolAddress((void**)&h1, g_h1);
    cudaGetSymbolAddress((void**)&x2, g_x2);
    cudaGetSymbolAddress((void**)&h2, g_h2);
    cudaGetSymbolAddress((void**)&x3, g_x3);
    cudaGetSymbolAddress((void**)&z4, g_z4);
    cudaGetSymbolAddress((void**)&sc1, g_sc1);
    cudaGetSymbolAddress((void**)&sc2, g_sc2);
    cudaGetSymbolAddress((void**)&mean, g_mean);
    cudaGetSymbolAddress((void**)&rstd, g_rstd);
    cudaGetSymbolAddress((void**)&bnp, g_bnpart);
    cudaGetSymbolAddress((void**)&part, g_part);
    cudaGetSymbolAddress((void**)&dp, g_dp);
    cudaGetSymbolAddress((void**)&h1th, g_h1th);
    cudaGetSymbolAddress((void**)&h1tl, g_h1tl);
    cudaGetSymbolAddress((void**)&h2th, g_h2th);
    cudaGetSymbolAddress((void**)&h2tl, g_h2tl);
    cudaGetSymbolAddress((void**)&ah, g_ah);
    cudaGetSymbolAddress((void**)&al, g_al);
    cudaGetSymbolAddress((void**)&wth, g_wth);
    cudaGetSymbolAddress((void**)&wtl, g_wtl);
    cudaGetSymbolAddress((void**)&lw1th, g_lw1th);
    cudaGetSymbolAddress((void**)&lw1tl, g_lw1tl);
    cudaGetSymbolAddress((void**)&w2th, g_w2th);
    cudaGetSymbolAddress((void**)&w2tl, g_w2tl);

    const int SMEM1 = 6 * F1 * 128 + 3072 + 1536;
    const int SMEM2 = 6 * F2 * 128 + 3072 + 1536;
    const int SMEMG128 = 3 * (2 * 16384 + 2 * 128 * 128);
    const int SMEMG64  = 3 * (2 * 16384 + 2 * 64 * 128);
    cudaFuncSetAttribute((const void*)k_gat_hmma<F1>,
                         cudaFuncAttributeMaxDynamicSharedMemorySize, SMEM1);
    cudaFuncSetAttribute((const void*)k_gat_hmma<F2>,
                         cudaFuncAttributeMaxDynamicSharedMemorySize, SMEM2);
    cudaFuncSetAttribute((const void*)k_gemm_hmma<128, 16>,
                         cudaFuncAttributeMaxDynamicSharedMemorySize, SMEMG128);
    cudaFuncSetAttribute((const void*)k_gemm_hmma<64, 8>,
                         cudaFuncAttributeMaxDynamicSharedMemorySize, SMEMG64);

    static cudaStream_t s2 = nullptr;
    static cudaEvent_t e0 = nullptr, e2 = nullptr, e3 = nullptr, e4 = nullptr, e5 = nullptr;
    if (!s2) {
        cudaStreamCreateWithFlags(&s2, cudaStreamNonBlocking);
        cudaEventCreateWithFlags(&e0, cudaEventDisableTiming);
        cudaEventCreateWithFlags(&e2, cudaEventDisableTiming);
        cudaEventCreateWithFlags(&e3, cudaEventDisableTiming);
        cudaEventCreateWithFlags(&e4, cudaEventDisableTiming);
        cudaEventCreateWithFlags(&e5, cudaEventDisableTiming);
    }

    cudaEventRecord(e0, 0);
    cudaStreamWaitEvent(s2, e0, 0);
    k_pack_mask<<<(NN * NN) / 256, 256, 0, s2>>>(adj);
    k_transpose_split<<<dim3(512 / 32, HID1 / 32), dim3(32, 8), 0, s2>>>(lw1, lw1th, lw1tl, 512, HID1);
    k_transpose_split<<<dim3(HID1 / 32, 128 / 32), dim3(32, 8), 0, s2>>>(W2, w2th, w2tl, HID1, 128);

    k_split_bf16<<<(NN * IN_F / 4) / 256, 256>>>(x, ah, al);
    k_transpose_split<<<dim3(IN_F / 32, 512 / 32), dim3(32, 8)>>>(W1, wth, wtl, IN_F, 512);
    k_gemm_hmma<128, 16><<<dim3(NN / 128, 512 / 128), 512, SMEMG128>>>(
        ah, al, wth, wtl, nullptr, h1, IN_F, 512);

    cudaEventRecord(e2, 0);
    cudaStreamWaitEvent(s2, e2, 0);
    k_transpose_split<<<dim3(NN / 32, 512 / 32), dim3(32, 8), 0, s2>>>(h1, h1th, h1tl, NN, 512);
    k_attn_scores<F1><<<NN / 8, 256>>>(h1, a1s, a1d, sc1);
    cudaEventRecord(e3, s2);
    cudaStreamWaitEvent(0, e3, 0);

    // gat1: K-split partials, then combine + normalize + split into ah/al
    k_gat_hmma<F1><<<dim3(NN / 128, H, 2), 256, SMEM1>>>(h1th, h1tl, sc1, part, dp);
    k_gat_fin<F1, true><<<(NN * 512 / 4) / 256, 256>>>(part, dp, nullptr, ah, al);

    k_gemm_hmma<64, 8><<<dim3(NN / 128, HID1 / 64), 256, SMEMG64>>>(
        ah, al, lw1th, lw1tl, lb1, x2, 512, HID1);

    k_bn_part<HID1><<<32, 256>>>(x2, bnp);
    k_bn_fin<HID1><<<1, 64>>>(bnp, mean, rstd);
    k_bn_elu_split<<<(NN * HID1) / 256, 256>>>(x2, mean, rstd, g1, be1, ah, al, HID1);

    k_gemm_hmma<128, 16><<<dim3(NN / 128, 1), 512, SMEMG128>>>(
        ah, al, w2th, w2tl, nullptr, h2, HID1, 128);

    cudaEventRecord(e4, 0);
    cudaStreamWaitEvent(s2, e4, 0);
    k_transpose_split<<<dim3(NN / 32, 128 / 32), dim3(32, 8), 0, s2>>>(h2, h2th, h2tl, NN, 128);
    k_attn_scores<F2><<<NN / 8, 256>>>(h2, a2s, a2d, sc2);
    cudaEventRecord(e5, s2);
    cudaStreamWaitEvent(0, e5, 0);

    // gat2: K-split partials, then combine + normalize into x3 (fp32)
    k_gat_hmma<F2><<<dim3(NN / 128, H, 2), 256, SMEM2>>>(h2th, h2tl, sc2, part, dp);
    k_gat_fin<F2, false><<<(NN * 128 / 4) / 256, 256>>>(part, dp, x3, nullptr, nullptr);

    k_gemm_bias<128, 16, 32, 4, 2><<<dim3(1, NN / 128), 256>>>(x3, lw2, lb2, z4, NN, OUT_F, 128);

    k_bn_part<OUT_F><<<32, 256>>>(z4, bnp);
    k_bn_fin<OUT_F><<<1, 64>>>(bnp, mean, rstd);
    k_bn_elu<<<(NN * OUT_F) / 256, 256>>>(z4, mean, rstd, g2, be2, out, OUT_F);
}

// round 14
// speedup vs baseline: 1.1002x; 1.1002x over previous
#include <cuda_runtime.h>
#include <cuda_bf16.h>
#include <cuda_fp16.h>
#include <math.h>
#include <stdint.h>

#define NN 4096
#define NW 128
#define H 4
#define F1 128
#define F2 32
#define HN (H * NN)
#define IN_F 512
#define HID1 64
#define OUT_F 16
#define LRELU 0.2f
#define BN_EPS 1e-5f

// ---------------- scratch ----------------
__device__ float         g_h1[NN * 512];
__device__ float         g_x2[NN * HID1];
__device__ float         g_h2[NN * 128];
__device__ float         g_x3[NN * 128];
__device__ float         g_z4[NN * OUT_F];
__device__ float         g_sc1[6 * HN];
__device__ float         g_sc2[6 * HN];
__device__ unsigned      g_mask[NN * NW];
__device__ float         g_mean[64], g_rstd[64];
__device__ float         g_bnpart[32 * 2 * 64];
__device__ float         g_part[2 * NN * 512];
__device__ float         g_dp[2 * HN];
__device__ __half        g_h1th[512 * NN];   // h1^T fp16 hi
__device__ __half        g_h1tl[512 * NN];   // h1^T fp16 lo
__device__ __half        g_h2th[128 * NN];
__device__ __half        g_h2tl[128 * NN];
__device__ __nv_bfloat16 g_ah[NN * 512];
__device__ __nv_bfloat16 g_al[NN * 512];
__device__ __nv_bfloat16 g_wth[512 * 512];
__device__ __nv_bfloat16 g_wtl[512 * 512];
__device__ __nv_bfloat16 g_lw1th[HID1 * 512];
__device__ __nv_bfloat16 g_lw1tl[HID1 * 512];
__device__ __nv_bfloat16 g_w2th[128 * HID1];
__device__ __nv_bfloat16 g_w2tl[128 * HID1];

// ================= helpers =================
__device__ __forceinline__ uint32_t smem_u32(const void* p) {
    uint32_t a;
    asm("{ .reg .u64 t; cvta.to.shared.u64 t, %1; cvt.u32.u64 %0, t; }" : "=r"(a) : "l"(p));
    return a;
}
__device__ __forceinline__ void cp16(uint32_t dst, const void* src) {
    asm volatile("cp.async.cg.shared.global [%0], [%1], 16;" :: "r"(dst), "l"(src));
}
__device__ __forceinline__ void cp8(uint32_t dst, const void* src) {
    asm volatile("cp.async.ca.shared.global [%0], [%1], 8;" :: "r"(dst), "l"(src));
}
#define CP_COMMIT() asm volatile("cp.async.commit_group;" ::: "memory")
#define CP_WAIT1()  asm volatile("cp.async.wait_group 1;" ::: "memory")

__device__ __forceinline__ void mma16816(float* c,
    uint32_t a0, uint32_t a1, uint32_t a2, uint32_t a3, uint32_t b0, uint32_t b1) {
    asm volatile(
        "mma.sync.aligned.m16n8k16.row.col.f32.bf16.bf16.f32 "
        "{%0,%1,%2,%3}, {%4,%5,%6,%7}, {%8,%9}, {%0,%1,%2,%3};"
        : "+f"(c[0]), "+f"(c[1]), "+f"(c[2]), "+f"(c[3])
        : "r"(a0), "r"(a1), "r"(a2), "r"(a3), "r"(b0), "r"(b1));
}
__device__ __forceinline__ void mma16816h(float* c,
    uint32_t a0, uint32_t a1, uint32_t a2, uint32_t a3, uint32_t b0, uint32_t b1) {
    asm volatile(
        "mma.sync.aligned.m16n8k16.row.col.f32.f16.f16.f32 "
        "{%0,%1,%2,%3}, {%4,%5,%6,%7}, {%8,%9}, {%0,%1,%2,%3};"
        : "+f"(c[0]), "+f"(c[1]), "+f"(c[2]), "+f"(c[3])
        : "r"(a0), "r"(a1), "r"(a2), "r"(a3), "r"(b0), "r"(b1));
}
__device__ __forceinline__ void ldsm4(uint32_t& r0, uint32_t& r1, uint32_t& r2, uint32_t& r3,
                                      uint32_t addr) {
    asm volatile("ldmatrix.sync.aligned.m8n8.x4.shared.b16 {%0,%1,%2,%3}, [%4];"
                 : "=r"(r0), "=r"(r1), "=r"(r2), "=r"(r3) : "r"(addr));
}
__device__ __forceinline__ float wmax(float E, float e, float Ev, float e2, unsigned bit) {
    float v = fmaxf(E * Ev, e * e2);
    return bit ? v : 0.f;
}
__device__ __forceinline__ uint32_t packh2(float a, float b) {
    __half2 h = __floats2half2_rn(a, b);
    return *(uint32_t*)&h;
}

// ---------------- adjacency -> bitmask ----------------
__global__ void k_pack_mask(const int* __restrict__ adj) {
    int gw   = (blockIdx.x * blockDim.x + threadIdx.x) >> 5;
    int lane = threadIdx.x & 31;
    int v = adj[(size_t)gw * 32 + lane];
    unsigned m = __ballot_sync(0xffffffffu, v > 0);
    if (lane == 0) g_mask[gw] = m;
}

// ---------------- elementwise fp32 -> bf16 hi/lo split ----------------
__global__ void k_split_bf16(const float* __restrict__ in,
                             __nv_bfloat16* __restrict__ oh,
                             __nv_bfloat16* __restrict__ ol) {
    int idx = blockIdx.x * blockDim.x + threadIdx.x;
    float4 v = ((const float4*)in)[idx];
    __nv_bfloat162 h0 = __floats2bfloat162_rn(v.x, v.y);
    __nv_bfloat162 h1 = __floats2bfloat162_rn(v.z, v.w);
    __nv_bfloat162 l0 = __floats2bfloat162_rn(v.x - __bfloat162float(h0.x),
                                              v.y - __bfloat162float(h0.y));
    __nv_bfloat162 l1 = __floats2bfloat162_rn(v.z - __bfloat162float(h1.x),
                                              v.w - __bfloat162float(h1.y));
    ((__nv_bfloat162*)oh)[idx * 2] = h0;
    ((__nv_bfloat162*)oh)[idx * 2 + 1] = h1;
    ((__nv_bfloat162*)ol)[idx * 2] = l0;
    ((__nv_bfloat162*)ol)[idx * 2 + 1] = l1;
}

// ---------------- transpose fp32 [R,C] -> bf16 hi/lo [C,R] (for GEMM weights) ----------------
__global__ void k_transpose_split(const float* __restrict__ in,
                                  __nv_bfloat16* __restrict__ oh,
                                  __nv_bfloat16* __restrict__ ol, int R, int C) {
    __shared__ float tile[32][33];
    int r0 = blockIdx.x * 32, c0 = blockIdx.y * 32;
    int tx = threadIdx.x, ty = threadIdx.y;
#pragma unroll
    for (int q = 0; q < 4; q++)
        tile[ty * 4 + q][tx] = in[(size_t)(r0 + ty * 4 + q) * C + c0 + tx];
    __syncthreads();
#pragma unroll
    for (int q = 0; q < 4; q++) {
        float v = tile[tx][ty * 4 + q];
        __nv_bfloat16 hi = __float2bfloat16(v);
        float lo = v - __bfloat162float(hi);
        size_t o = (size_t)(c0 + ty * 4 + q) * R + r0 + tx;
        oh[o] = hi;
        ol[o] = __float2bfloat16(lo);
    }
}

// ---------------- transpose fp32 [R,C] -> fp16 hi/lo [C,R] (for GAT h tiles) ----------------
__global__ void k_transpose_split_f16(const float* __restrict__ in,
                                      __half* __restrict__ oh,
                                      __half* __restrict__ ol, int R, int C) {
    __shared__ float tile[32][33];
    int r0 = blockIdx.x * 32, c0 = blockIdx.y * 32;
    int tx = threadIdx.x, ty = threadIdx.y;
#pragma unroll
    for (int q = 0; q < 4; q++)
        tile[ty * 4 + q][tx] = in[(size_t)(r0 + ty * 4 + q) * C + c0 + tx];
    __syncthreads();
#pragma unroll
    for (int q = 0; q < 4; q++) {
        float v = tile[tx][ty * 4 + q];
        __half hi = __float2half_rn(v);
        float lo = v - __half2float(hi);
        size_t o = (size_t)(c0 + ty * 4 + q) * R + r0 + tx;
        oh[o] = hi;
        ol[o] = __float2half_rn(lo);
    }
}

// ================ split-bf16 HMMA GEMM, 3-stage pipeline ================
template <int BN, int NWARP>
__device__ __forceinline__ void gemm_load(int t, int m0, int n0, int c, int buf,
                                          uint32_t sb, int K,
                                          const __nv_bfloat16* Ah, const __nv_bfloat16* Al,
                                          const __nv_bfloat16* Bh, const __nv_bfloat16* Bl) {
    constexpr int AB = 16384;
    constexpr int BB = BN * 128;
    constexpr int STAGE = 2 * AB + 2 * BB;
    uint32_t base = sb + buf * STAGE;
#pragma unroll
    for (int idx = t; idx < 1024; idx += NWARP * 32) {
        int m = idx >> 3, q = idx & 7;
        uint32_t off = base + (uint32_t)(m * 128 + ((q ^ (m & 7)) << 4));
        size_t src = (size_t)(m0 + m) * K + c * 64 + q * 8;
        cp16(off, Ah + src);
        cp16(off + AB, Al + src);
    }
#pragma unroll
    for (int idx = t; idx < BN * 8; idx += NWARP * 32) {
        int n = idx >> 3, q = idx & 7;
        uint32_t off = base + 2 * AB + (uint32_t)(n * 128 + ((q ^ (n & 7)) << 4));
        size_t src = (size_t)(n0 + n) * K + c * 64 + q * 8;
        cp16(off, Bh + src);
        cp16(off + BB, Bl + src);
    }
}

template <int BN, int NWARP>
__global__ __launch_bounds__(NWARP * 32) void k_gemm_hmma(
    const __nv_bfloat16* __restrict__ Ah, const __nv_bfloat16* __restrict__ Al,
    const __nv_bfloat16* __restrict__ Bh, const __nv_bfloat16* __restrict__ Bl,
    const float* __restrict__ bias, float* __restrict__ C, int K, int Ntot) {
    constexpr int AB = 16384;
    constexpr int BB = BN * 128;
    constexpr int STAGE = 2 * AB + 2 * BB;
    extern __shared__ char sm[];
    uint32_t sb = smem_u32(sm);
    int t = threadIdx.x, wid = t >> 5, lane = t & 31;
    int m0 = blockIdx.x * 128, n0 = blockIdx.y * BN;
    int wm = (wid & 3) * 32, wn = (wid >> 2) * 32;
    int g = lane >> 2, tig = lane & 3;
    int nc = K >> 6;

    int arow = (lane & 7) + ((lane >> 3) & 1) * 8;
    int ahalf = lane >> 4;
    int brow = ((lane >> 4) << 3) + (lane & 7);
    int bhalf = (lane >> 3) & 1;

    float acc[2][4][4];
#pragma unroll
    for (int mt = 0; mt < 2; mt++)
#pragma unroll
        for (int nt = 0; nt < 4; nt++)
#pragma unroll
            for (int q = 0; q < 4; q++) acc[mt][nt][q] = 0.f;

    gemm_load<BN, NWARP>(t, m0, n0, 0, 0, sb, K, Ah, Al, Bh, Bl);
    CP_COMMIT();
    if (nc > 1) gemm_load<BN, NWARP>(t, m0, n0, 1, 1, sb, K, Ah, Al, Bh, Bl);
    CP_COMMIT();

    for (int c = 0; c < nc; c++) {
        int buf = c % 3;
        CP_WAIT1();
        __syncthreads();
        if (c + 2 < nc)
            gemm_load<BN, NWARP>(t, m0, n0, c + 2, (c + 2) % 3, sb, K, Ah, Al, Bh, Bl);
        CP_COMMIT();
        uint32_t base = sb + buf * STAGE;
#pragma unroll
        for (int ks = 0; ks < 4; ks++) {
            uint32_t ahf[2][4], alf[2][4], bhf[2][4], blf[2][4];
#pragma unroll
            for (int mt = 0; mt < 2; mt++) {
                int r = wm + mt * 16 + arow;
                int slot = 2 * ks + ahalf;
                uint32_t ad = base + (uint32_t)(r * 128 + ((slot ^ (r & 7)) << 4));
                ldsm4(ahf[mt][0], ahf[mt][1], ahf[mt][2], ahf[mt][3], ad);
                ldsm4(alf[mt][0], alf[mt][1], alf[mt][2], alf[mt][3], ad + AB);
            }
#pragma unroll
            for (int np = 0; np < 2; np++) {
                int r = wn + np * 16 + brow;
                int slot = 2 * ks + bhalf;
                uint32_t bd = base + 2 * AB + (uint32_t)(r * 128 + ((slot ^ (r & 7)) << 4));
                ldsm4(bhf[np][0], bhf[np][1], bhf[np][2], bhf[np][3], bd);
                ldsm4(blf[np][0], blf[np][1], blf[np][2], blf[np][3], bd + BB);
            }
#pragma unroll
            for (int mt = 0; mt < 2; mt++)
#pragma unroll
                for (int nt = 0; nt < 4; nt++) {
                    int np = nt >> 1, sel = (nt & 1) * 2;
                    mma16816(acc[mt][nt], ahf[mt][0], ahf[mt][1], ahf[mt][2], ahf[mt][3],
                             bhf[np][sel], bhf[np][sel + 1]);
                }
#pragma unroll
            for (int mt = 0; mt < 2; mt++)
#pragma unroll
                for (int nt = 0; nt < 4; nt++) {
                    int np = nt >> 1, sel = (nt & 1) * 2;
                    mma16816(acc[mt][nt], ahf[mt][0], ahf[mt][1], ahf[mt][2], ahf[mt][3],
                             blf[np][sel], blf[np][sel + 1]);
                }
#pragma unroll
            for (int mt = 0; mt < 2; mt++)
#pragma unroll
                for (int nt = 0; nt < 4; nt++) {
                    int np = nt >> 1, sel = (nt & 1) * 2;
                    mma16816(acc[mt][nt], alf[mt][0], alf[mt][1], alf[mt][2], alf[mt][3],
                             bhf[np][sel], bhf[np][sel + 1]);
                }
        }
    }
#pragma unroll
    for (int mt = 0; mt < 2; mt++)
#pragma unroll
        for (int nt = 0; nt < 4; nt++) {
            int row = m0 + wm + mt * 16 + g;
            int col = n0 + wn + nt * 8 + tig * 2;
            float bv0 = bias ? bias[col] : 0.f;
            float bv1 = bias ? bias[col + 1] : 0.f;
            float2 v0 = make_float2(acc[mt][nt][0] + bv0, acc[mt][nt][1] + bv1);
            float2 v1 = make_float2(acc[mt][nt][2] + bv0, acc[mt][nt][3] + bv1);
            *(float2*)&C[(size_t)row * Ntot + col] = v0;
            *(float2*)&C[(size_t)(row + 8) * Ntot + col] = v1;
        }
}

// ---------------- fp32 GEMM for lin2 ----------------
template <int BM, int BN, int BK, int TM, int TN>
__global__ void k_gemm_bias(const float* __restrict__ A, const float* __restrict__ B,
                            const float* __restrict__ bias, float* __restrict__ C,
                            int M, int Nn, int K) {
    constexpr int THREADS = (BM / TM) * (BN / TN);
    __shared__ float As[BM][BK + 1];
    __shared__ float Bs[BK][BN + 1];
    int tid = threadIdx.x;
    int rm = tid / (BN / TN);
    int rn = tid % (BN / TN);
    int m0 = blockIdx.y * BM, n0 = blockIdx.x * BN;
    float acc[TM][TN];
#pragma unroll
    for (int m = 0; m < TM; m++)
#pragma unroll
        for (int n = 0; n < TN; n++) acc[m][n] = 0.f;

    for (int k0 = 0; k0 < K; k0 += BK) {
        for (int idx = tid; idx < BM * BK; idx += THREADS) {
            int r = idx / BK, c = idx % BK;
            As[r][c] = A[(size_t)(m0 + r) * K + k0 + c];
        }
        for (int idx = tid; idx < BK * BN; idx += THREADS) {
            int r = idx / BN, c = idx % BN;
            Bs[r][c] = B[(size_t)(k0 + r) * Nn + n0 + c];
        }
        __syncthreads();
#pragma unroll
        for (int kk = 0; kk < BK; kk++) {
            float a[TM], b[TN];
#pragma unroll
            for (int m = 0; m < TM; m++) a[m] = As[rm * TM + m][kk];
#pragma unroll
            for (int n = 0; n < TN; n++) b[n] = Bs[kk][rn * TN + n];
#pragma unroll
            for (int m = 0; m < TM; m++)
#pragma unroll
                for (int n = 0; n < TN; n++) acc[m][n] = fmaf(a[m], b[n], acc[m][n]);
        }
        __syncthreads();
    }
#pragma unroll
    for (int m = 0; m < TM; m++) {
        int row = m0 + rm * TM + m;
#pragma unroll
        for (int n = 0; n < TN; n++) {
            int col = n0 + rn * TN + n;
            float v = acc[m][n];
            if (bias) v += bias[col];
            C[(size_t)row * Nn + col] = v;
        }
    }
}

// ---------------- per-node scores + precomputed exps ----------------
template <int F>
__global__ void k_attn_scores(const float* __restrict__ hfeat,
                              const float* __restrict__ a_src,
                              const float* __restrict__ a_dst,
                              float* __restrict__ sc) {
    int n = blockIdx.x * (blockDim.x >> 5) + (threadIdx.x >> 5);
    int lane = threadIdx.x & 31;
    if (n >= NN) return;
    const float* row = hfeat + (size_t)n * (H * F);
#pragma unroll
    for (int h = 0; h < H; h++) {
        float ss = 0.f, sd = 0.f;
        for (int k = lane; k < F; k += 32) {
            float v = row[h * F + k];
            ss = fmaf(v, a_src[h * F + k], ss);
            sd = fmaf(v, a_dst[h * F + k], sd);
        }
#pragma unroll
        for (int o = 16; o; o >>= 1) {
            ss += __shfl_xor_sync(0xffffffffu, ss, o);
            sd += __shfl_xor_sync(0xffffffffu, sd, o);
        }
        if (lane == 0) {
            int idx = h * NN + n;
            sc[0 * HN + idx] = ss;
            sc[1 * HN + idx] = expf(ss);
            sc[2 * HN + idx] = expf(LRELU * ss);
            sc[3 * HN + idx] = sd;
            sc[4 * HN + idx] = expf(sd);
            sc[5 * HN + idx] = expf(LRELU * sd);
        }
    }
}

// ================ GAT aggregation: fp16 A (single) x fp16 B (hi+lo), 2 MMAs ================
template <int F>
__device__ __forceinline__ void load_chunk(int t, int head, int i0, int c, int buf,
                                           char* BtB, unsigned* mk, float* edb,
                                           const __half* hTh,
                                           const __half* hTl,
                                           const float* sc) {
    constexpr int BT = F * 128;
    char* dsthi = BtB + buf * 2 * BT;
    char* dstlo = dsthi + BT;
    for (int idx = t; idx < F * 8; idx += 256) {
        int f = idx >> 3, q = idx & 7;
        uint32_t off = (uint32_t)(f * 128 + (((q ^ (f & 7)) << 4)));
        size_t src = (size_t)(head * F + f) * NN + c * 64 + q * 8;
        cp16(smem_u32(dsthi + off), hTh + src);
        cp16(smem_u32(dstlo + off), hTl + src);
    }
    if (t < 128) cp8(smem_u32(mk + buf * 256 + t * 2), &g_mask[(size_t)(i0 + t) * NW + c * 2]);
    if (t < 32) {
        int a = t >> 4, q = t & 15;
        cp16(smem_u32(edb + buf * 128 + a * 64 + q * 4),
             &sc[(size_t)(4 + a) * HN + head * NN + c * 64 + q * 4]);
    }
}

template <int F>
__global__ __launch_bounds__(256) void k_gat_hmma(const __half* __restrict__ hTh,
                                                  const __half* __restrict__ hTl,
                                                  const float* __restrict__ sc,
                                                  float* __restrict__ part,
                                                  float* __restrict__ dp) {
    constexpr int BT = F * 128;
    constexpr int MPF = F / 16;
    extern __shared__ char smem[];
    char* BtB = smem;
    unsigned* mk = (unsigned*)(smem + 6 * BT);
    float* edb = (float*)(smem + 6 * BT + 3072);

    int t = threadIdx.x, wid = t >> 5, lane = t & 31;
    int g = lane >> 2, tig = lane & 3;
    int head = blockIdx.y, i0 = blockIdx.x * 128;
    int z = blockIdx.z;
    int c0 = z * 32;
    uint32_t sb = smem_u32(smem);

    int r0 = wid * 16 + g, r1 = r0 + 8;
    const float* scb = sc + head * NN + i0;
    float E0 = scb[HN + r0], e0 = scb[2 * HN + r0];
    float E1 = scb[HN + r1], e1 = scb[2 * HN + r1];

    int flr = ((lane >> 4) & 1) * 8 + (lane & 7);
    int qb = (lane >> 3) & 1;
    int sxw = flr & 7;
    uint32_t fcol = (uint32_t)(flr * 128);

    float acc[2 * MPF][4];
#pragma unroll
    for (int nt = 0; nt < 2 * MPF; nt++)
#pragma unroll
        for (int q = 0; q < 4; q++) acc[nt][q] = 0.f;
    float d0 = 0.f, d1 = 0.f;

    load_chunk<F>(t, head, i0, c0, 0, BtB, mk, edb, hTh, hTl, sc);
    CP_COMMIT();
    load_chunk<F>(t, head, i0, c0 + 1, 1, BtB, mk, edb, hTh, hTl, sc);
    CP_COMMIT();

    for (int cc = 0; cc < 32; cc++) {
        int b = cc % 3;
        CP_WAIT1();
        __syncthreads();
        if (cc < 30)
            load_chunk<F>(t, head, i0, c0 + cc + 2, (cc + 2) % 3, BtB, mk, edb, hTh, hTl, sc);
        CP_COMMIT();
        unsigned* mkb = mk + b * 256;
        unsigned m0a = mkb[r0 * 2], m0b = mkb[r0 * 2 + 1];
        unsigned m1a = mkb[r1 * 2], m1b = mkb[r1 * 2 + 1];
        float* ed = edb + b * 128;
        uint32_t bufbase = sb + (uint32_t)(b * 2 * BT);
#pragma unroll
        for (int ks = 0; ks < 4; ks++) {
            int jb = ks * 16 + tig * 2;
            float2 EvL = *(float2*)&ed[jb];
            float2 EvH = *(float2*)&ed[jb + 8];
            float2 e2L = *(float2*)&ed[64 + jb];
            float2 e2H = *(float2*)&ed[64 + jb + 8];
            int bit = (ks & 1) * 16 + tig * 2;
            unsigned w0 = (ks < 2) ? m0a : m0b;
            unsigned w1 = (ks < 2) ? m1a : m1b;

            float a0 = wmax(E0, e0, EvL.x, e2L.x, (w0 >> bit) & 1u);
            float a1 = wmax(E0, e0, EvL.y, e2L.y, (w0 >> (bit + 1)) & 1u);
            float a2 = wmax(E0, e0, EvH.x, e2H.x, (w0 >> (bit + 8)) & 1u);
            float a3 = wmax(E0, e0, EvH.y, e2H.y, (w0 >> (bit + 9)) & 1u);
            float b0 = wmax(E1, e1, EvL.x, e2L.x, (w1 >> bit) & 1u);
            float b1 = wmax(E1, e1, EvL.y, e2L.y, (w1 >> (bit + 1)) & 1u);
            float b2 = wmax(E1, e1, EvH.x, e2H.x, (w1 >> (bit + 8)) & 1u);
            float b3 = wmax(E1, e1, EvH.y, e2H.y, (w1 >> (bit + 9)) & 1u);
            d0 += a0 + a1 + a2 + a3;
            d1 += b0 + b1 + b2 + b3;
            uint32_t A0 = packh2(a0, a1);
            uint32_t A1 = packh2(b0, b1);
            uint32_t A2 = packh2(a2, a3);
            uint32_t A3 = packh2(b2, b3);

            uint32_t swz = (uint32_t)((((2 * ks + qb) ^ sxw) << 4));
#pragma unroll
            for (int mp = 0; mp < MPF; mp++) {
                uint32_t ad = bufbase + fcol + (uint32_t)(mp * 2048) + swz;
                uint32_t bh0, bh1, bh2, bh3, bl0, bl1, bl2, bl3;
                ldsm4(bh0, bh1, bh2, bh3, ad);
                ldsm4(bl0, bl1, bl2, bl3, ad + BT);
                float* c0a = acc[2 * mp];
                float* c1a = acc[2 * mp + 1];
                mma16816h(c0a, A0, A1, A2, A3, bh0, bh1);
                mma16816h(c1a, A0, A1, A2, A3, bh2, bh3);
                mma16816h(c0a, A0, A1, A2, A3, bl0, bl1);
                mma16816h(c1a, A0, A1, A2, A3, bl2, bl3);
            }
        }
    }
    d0 += __shfl_xor_sync(0xffffffffu, d0, 1);
    d0 += __shfl_xor_sync(0xffffffffu, d0, 2);
    d1 += __shfl_xor_sync(0xffffffffu, d1, 1);
    d1 += __shfl_xor_sync(0xffffffffu, d1, 2);
    if (tig == 0) {
        dp[(size_t)z * HN + head * NN + i0 + r0] = d0;
        dp[(size_t)z * HN + head * NN + i0 + r1] = d1;
    }
    float* pz = part + (size_t)z * NN * (H * F);
#pragma unroll
    for (int nt = 0; nt < 2 * MPF; nt++) {
        int col = head * F + nt * 8 + tig * 2;
        *(float2*)&pz[(size_t)(i0 + r0) * (H * F) + col] = make_float2(acc[nt][0], acc[nt][1]);
        *(float2*)&pz[(size_t)(i0 + r1) * (H * F) + col] = make_float2(acc[nt][2], acc[nt][3]);
    }
}

// ---- combine K-split partials, normalize, optional bf16 split output ----
template <int F, bool SPLIT>
__global__ void k_gat_fin(const float* __restrict__ part, const float* __restrict__ dp,
                          float* __restrict__ out,
                          __nv_bfloat16* __restrict__ oh, __nv_bfloat16* __restrict__ ol) {
    constexpr int HF = H * F;
    int idx = blockIdx.x * blockDim.x + threadIdx.x;
    int e0 = idx * 4;
    int row = e0 / HF, cc = e0 % HF, head = cc / F;
    float inv = 1.f / (dp[head * NN + row] + dp[HN + head * NN + row]);
    float4 p0 = ((const float4*)part)[idx];
    float4 p1 = ((const float4*)(part + (size_t)NN * HF))[idx];
    float v0 = (p0.x + p1.x) * inv, v1 = (p0.y + p1.y) * inv;
    float v2 = (p0.z + p1.z) * inv, v3 = (p0.w + p1.w) * inv;
    if (SPLIT) {
        __nv_bfloat162 h0 = __floats2bfloat162_rn(v0, v1);
        __nv_bfloat162 h1 = __floats2bfloat162_rn(v2, v3);
        __nv_bfloat162 l0 = __floats2bfloat162_rn(v0 - __bfloat162float(h0.x),
                                                  v1 - __bfloat162float(h0.y));
        __nv_bfloat162 l1 = __floats2bfloat162_rn(v2 - __bfloat162float(h1.x),
                                                  v3 - __bfloat162float(h1.y));
        ((__nv_bfloat162*)oh)[idx * 2] = h0;
        ((__nv_bfloat162*)oh)[idx * 2 + 1] = h1;
        ((__nv_bfloat162*)ol)[idx * 2] = l0;
        ((__nv_bfloat162*)ol)[idx * 2 + 1] = l1;
    } else {
        ((float4*)out)[idx] = make_float4(v0, v1, v2, v3);
    }
}

// ---------------- batchnorm ----------------
template <int C>
__global__ void k_bn_part(const float* __restrict__ z, float* __restrict__ part) {
    constexpr int RL = 256 / C;
    int blk = blockIdx.x;
    int t = threadIdx.x;
    int col = t % C, rl = t / C;
    float s = 0.f, s2 = 0.f;
    for (int r = rl; r < 128; r += RL) {
        float v = z[(size_t)(blk * 128 + r) * C + col];
        s += v; s2 += v * v;
    }
    __shared__ float sh[256], sh2[256];
    sh[t] = s; sh2[t] = s2;
    __syncthreads();
    if (rl == 0) {
#pragma unroll
        for (int q = 1; q < RL; q++) { s += sh[q * C + col]; s2 += sh2[q * C + col]; }
        part[blk * 2 * C + col] = s;
        part[blk * 2 * C + C + col] = s2;
    }
}
template <int C>
__global__ void k_bn_fin(const float* __restrict__ part,
                         float* __restrict__ mean, float* __restrict__ rstd) {
    int c = threadIdx.x;
    if (c >= C) return;
    double s = 0.0, s2 = 0.0;
    for (int b = 0; b < 32; b++) { s += part[b * 2 * C + c]; s2 += part[b * 2 * C + C + c]; }
    double mu = s / NN;
    double var = s2 / NN - mu * mu;
    mean[c] = (float)mu;
    rstd[c] = rsqrtf((float)var + BN_EPS);
}

__global__ void k_bn_elu(const float* __restrict__ z, const float* __restrict__ mean,
                         const float* __restrict__ rstd, const float* __restrict__ gamma,
                         const float* __restrict__ beta, float* __restrict__ out, int C) {
    int idx = blockIdx.x * blockDim.x + threadIdx.x;
    int c = idx % C;
    float v = (z[idx] - mean[c]) * rstd[c] * gamma[c] + beta[c];
    out[idx] = v > 0.f ? v : (expf(v) - 1.f);
}

__global__ void k_bn_elu_split(const float* __restrict__ z, const float* __restrict__ mean,
                               const float* __restrict__ rstd, const float* __restrict__ gamma,
                               const float* __restrict__ beta,
                               __nv_bfloat16* __restrict__ oh, __nv_bfloat16* __restrict__ ol,
                               int C) {
    int idx = blockIdx.x * blockDim.x + threadIdx.x;
    int c = idx % C;
    float v = (z[idx] - mean[c]) * rstd[c] * gamma[c] + beta[c];
    v = v > 0.f ? v : (expf(v) - 1.f);
    __nv_bfloat16 hi = __float2bfloat16(v);
    oh[idx] = hi;
    ol[idx] = __float2bfloat16(v - __bfloat162float(hi));
}

// ---------------- launch ----------------
extern "C" void kernel_launch(void* const* d_in, const int* in_sizes, int n_in,
                              void* d_out, int out_size) {
    const float* x   = (const float*)d_in[0];
    const int*   adj = (const int*)d_in[1];
    const float* W1  = (const float*)d_in[2];
    const float* a1s = (const float*)d_in[3];
    const float* a1d = (const float*)d_in[4];
    const float* lw1 = (const float*)d_in[5];
    const float* lb1 = (const float*)d_in[6];
    const float* g1  = (const float*)d_in[7];
    const float* be1 = (const float*)d_in[8];
    const float* W2  = (const float*)d_in[9];
    const float* a2s = (const float*)d_in[10];
    const float* a2d = (const float*)d_in[11];
    const float* lw2 = (const float*)d_in[12];
    const float* lb2 = (const float*)d_in[13];
    const float* g2  = (const float*)d_in[14];
    const float* be2 = (const float*)d_in[15];
    float* out = (float*)d_out;

    float *h1, *x2, *h2, *x3, *z4, *sc1, *sc2, *mean, *rstd, *bnp, *part, *dp;
    __half *h1th, *h1tl, *h2th, *h2tl;
    __nv_bfloat16 *ah, *al, *wth, *wtl, *lw1th, *lw1tl, *w2th, *w2tl;
    cudaGetSymbolAddress((void**)&h1, g_h1);
    cudaGetSymbolAddress((void**)&x2, g_x2);
    cudaGetSymbolAddress((void**)&h2, g_h2);
    cudaGetSymbolAddress((void**)&x3, g_x3);
    cudaGetSymbolAddress((void**)&z4, g_z4);
    cudaGetSymbolAddress((void**)&sc1, g_sc1);
    cudaGetSymbolAddress((void**)&sc2, g_sc2);
    cudaGetSymbolAddress((void**)&mean, g_mean);
    cudaGetSymbolAddress((void**)&rstd, g_rstd);
    cudaGetSymbolAddress((void**)&bnp, g_bnpart);
    cudaGetSymbolAddress((void**)&part, g_part);
    cudaGetSymbolAddress((void**)&dp, g_dp);
    cudaGetSymbolAddress((void**)&h1th, g_h1th);
    cudaGetSymbolAddress((void**)&h1tl, g_h1tl);
    cudaGetSymbolAddress((void**)&h2th, g_h2th);
    cudaGetSymbolAddress((void**)&h2tl, g_h2tl);
    cudaGetSymbolAddress((void**)&ah, g_ah);
    cudaGetSymbolAddress((void**)&al, g_al);
    cudaGetSymbolAddress((void**)&wth, g_wth);
    cudaGetSymbolAddress((void**)&wtl, g_wtl);
    cudaGetSymbolAddress((void**)&lw1th, g_lw1th);
    cudaGetSymbolAddress((void**)&lw1tl, g_lw1tl);
    cudaGetSymbolAddress((void**)&w2th, g_w2th);
    cudaGetSymbolAddress((void**)&w2tl, g_w2tl);

    const int SMEM1 = 6 * F1 * 128 + 3072 + 1536;
    const int SMEM2 = 6 * F2 * 128 + 3072 + 1536;
    const int SMEMG128 = 3 * (2 * 16384 + 2 * 128 * 128);
    const int SMEMG64  = 3 * (2 * 16384 + 2 * 64 * 128);
    cudaFuncSetAttribute((const void*)k_gat_hmma<F1>,
                         cudaFuncAttributeMaxDynamicSharedMemorySize, SMEM1);
    cudaFuncSetAttribute((const void*)k_gat_hmma<F2>,
                         cudaFuncAttributeMaxDynamicSharedMemorySize, SMEM2);
    cudaFuncSetAttribute((const void*)k_gemm_hmma<128, 16>,
                         cudaFuncAttributeMaxDynamicSharedMemorySize, SMEMG128);
    cudaFuncSetAttribute((const void*)k_gemm_hmma<64, 8>,
                         cudaFuncAttributeMaxDynamicSharedMemorySize, SMEMG64);

    static cudaStream_t s2 = nullptr;
    static cudaEvent_t e0 = nullptr, e2 = nullptr, e3 = nullptr, e4 = nullptr, e5 = nullptr;
    if (!s2) {
        cudaStreamCreateWithFlags(&s2, cudaStreamNonBlocking);
        cudaEventCreateWithFlags(&e0, cudaEventDisableTiming);
        cudaEventCreateWithFlags(&e2, cudaEventDisableTiming);
        cudaEventCreateWithFlags(&e3, cudaEventDisableTiming);
        cudaEventCreateWithFlags(&e4, cudaEventDisableTiming);
        cudaEventCreateWithFlags(&e5, cudaEventDisableTiming);
    }

    cudaEventRecord(e0, 0);
    cudaStreamWaitEvent(s2, e0, 0);
    k_pack_mask<<<(NN * NN) / 256, 256, 0, s2>>>(adj);
    k_transpose_split<<<dim3(512 / 32, HID1 / 32), dim3(32, 8), 0, s2>>>(lw1, lw1th, lw1tl, 512, HID1);
    k_transpose_split<<<dim3(HID1 / 32, 128 / 32), dim3(32, 8), 0, s2>>>(W2, w2th, w2tl, HID1, 128);

    k_split_bf16<<<(NN * IN_F / 4) / 256, 256>>>(x, ah, al);
    k_transpose_split<<<dim3(IN_F / 32, 512 / 32), dim3(32, 8)>>>(W1, wth, wtl, IN_F, 512);
    k_gemm_hmma<128, 16><<<dim3(NN / 128, 512 / 128), 512, SMEMG128>>>(
        ah, al, wth, wtl, nullptr, h1, IN_F, 512);

    cudaEventRecord(e2, 0);
    cudaStreamWaitEvent(s2, e2, 0);
    k_transpose_split_f16<<<dim3(NN / 32, 512 / 32), dim3(32, 8), 0, s2>>>(h1, h1th, h1tl, NN, 512);
    k_attn_scores<F1><<<NN / 8, 256>>>(h1, a1s, a1d, sc1);
    cudaEventRecord(e3, s2);
    cudaStreamWaitEvent(0, e3, 0);

    k_gat_hmma<F1><<<dim3(NN / 128, H, 2), 256, SMEM1>>>(h1th, h1tl, sc1, part, dp);
    k_gat_fin<F1, true><<<(NN * 512 / 4) / 256, 256>>>(part, dp, nullptr, ah, al);

    k_gemm_hmma<64, 8><<<dim3(NN / 128, HID1 / 64), 256, SMEMG64>>>(
        ah, al, lw1th, lw1tl, lb1, x2, 512, HID1);

    k_bn_part<HID1><<<32, 256>>>(x2, bnp);
    k_bn_fin<HID1><<<1, 64>>>(bnp, mean, rstd);
    k_bn_elu_split<<<(NN * HID1) / 256, 256>>>(x2, mean, rstd, g1, be1, ah, al, HID1);

    k_gemm_hmma<128, 16><<<dim3(NN / 128, 1), 512, SMEMG128>>>(
        ah, al, w2th, w2tl, nullptr, h2, HID1, 128);

    cudaEventRecord(e4, 0);
    cudaStreamWaitEvent(s2, e4, 0);
    k_transpose_split_f16<<<dim3(NN / 32, 128 / 32), dim3(32, 8), 0, s2>>>(h2, h2th, h2tl, NN, 128);
    k_attn_scores<F2><<<NN / 8, 256>>>(h2, a2s, a2d, sc2);
    cudaEventRecord(e5, s2);
    cudaStreamWaitEvent(0, e5, 0);

    k_gat_hmma<F2><<<dim3(NN / 128, H, 2), 256, SMEM2>>>(h2th, h2tl, sc2, part, dp);
    k_gat_fin<F2, false><<<(NN * 128 / 4) / 256, 256>>>(part, dp, x3, nullptr, nullptr);

    k_gemm_bias<128, 16, 32, 4, 2><<<dim3(1, NN / 128), 256>>>(x3, lw2, lb2, z4, NN, OUT_F, 128);

    k_bn_part<OUT_F><<<32, 256>>>(z4, bnp);
    k_bn_fin<OUT_F><<<1, 64>>>(bnp, mean, rstd);
    k_bn_elu<<<(NN * OUT_F) / 256, 256>>>(z4, mean, rstd, g2, be2, out, OUT_F);
}

// round 15
// speedup vs baseline: 1.3859x; 1.2597x over previous
#include <cuda_runtime.h>
#include <cuda_bf16.h>
#include <cuda_fp16.h>
#include <math.h>
#include <stdint.h>

#define NN 4096
#define NW 128
#define H 4
#define F1 128
#define F2 32
#define HN (H * NN)
#define IN_F 512
#define HID1 64
#define OUT_F 16
#define LRELU 0.2f
#define BN_EPS 1e-5f

// ---------------- scratch ----------------
__device__ float         g_h1[NN * 512];
__device__ float         g_x2[NN * HID1];
__device__ float         g_h2[NN * 128];
__device__ float         g_x3[NN * 128];
__device__ float         g_z4[NN * OUT_F];
__device__ float         g_sc1[6 * HN];
__device__ float         g_sc2[6 * HN];
__device__ unsigned      g_mask[NN * NW];
__device__ float         g_mean[64], g_rstd[64];
__device__ float         g_bnpart[32 * 2 * 64];
__device__ float         g_part[2 * NN * 512];
__device__ float         g_dp[2 * HN];
__device__ __half        g_h1th[512 * NN];   // h1^T fp16
__device__ __half        g_h2th[128 * NN];   // h2^T fp16
__device__ __nv_bfloat16 g_ah[NN * 512];
__device__ __nv_bfloat16 g_al[NN * 512];
__device__ __nv_bfloat16 g_wth[512 * 512];
__device__ __nv_bfloat16 g_wtl[512 * 512];
__device__ __nv_bfloat16 g_lw1th[HID1 * 512];
__device__ __nv_bfloat16 g_lw1tl[HID1 * 512];
__device__ __nv_bfloat16 g_w2th[128 * HID1];
__device__ __nv_bfloat16 g_w2tl[128 * HID1];

// ================= helpers =================
__device__ __forceinline__ uint32_t smem_u32(const void* p) {
    uint32_t a;
    asm("{ .reg .u64 t; cvta.to.shared.u64 t, %1; cvt.u32.u64 %0, t; }" : "=r"(a) : "l"(p));
    return a;
}
__device__ __forceinline__ void cp16(uint32_t dst, const void* src) {
    asm volatile("cp.async.cg.shared.global [%0], [%1], 16;" :: "r"(dst), "l"(src));
}
__device__ __forceinline__ void cp8(uint32_t dst, const void* src) {
    asm volatile("cp.async.ca.shared.global [%0], [%1], 8;" :: "r"(dst), "l"(src));
}
#define CP_COMMIT() asm volatile("cp.async.commit_group;" ::: "memory")
#define CP_WAIT1()  asm volatile("cp.async.wait_group 1;" ::: "memory")

__device__ __forceinline__ void mma16816(float* c,
    uint32_t a0, uint32_t a1, uint32_t a2, uint32_t a3, uint32_t b0, uint32_t b1) {
    asm volatile(
        "mma.sync.aligned.m16n8k16.row.col.f32.bf16.bf16.f32 "
        "{%0,%1,%2,%3}, {%4,%5,%6,%7}, {%8,%9}, {%0,%1,%2,%3};"
        : "+f"(c[0]), "+f"(c[1]), "+f"(c[2]), "+f"(c[3])
        : "r"(a0), "r"(a1), "r"(a2), "r"(a3), "r"(b0), "r"(b1));
}
__device__ __forceinline__ void mma16816h(float* c,
    uint32_t a0, uint32_t a1, uint32_t a2, uint32_t a3, uint32_t b0, uint32_t b1) {
    asm volatile(
        "mma.sync.aligned.m16n8k16.row.col.f32.f16.f16.f32 "
        "{%0,%1,%2,%3}, {%4,%5,%6,%7}, {%8,%9}, {%0,%1,%2,%3};"
        : "+f"(c[0]), "+f"(c[1]), "+f"(c[2]), "+f"(c[3])
        : "r"(a0), "r"(a1), "r"(a2), "r"(a3), "r"(b0), "r"(b1));
}
__device__ __forceinline__ void ldsm4(uint32_t& r0, uint32_t& r1, uint32_t& r2, uint32_t& r3,
                                      uint32_t addr) {
    asm volatile("ldmatrix.sync.aligned.m8n8.x4.shared.b16 {%0,%1,%2,%3}, [%4];"
                 : "=r"(r0), "=r"(r1), "=r"(r2), "=r"(r3) : "r"(addr));
}
__device__ __forceinline__ float wmax(float E, float e, float Ev, float e2, unsigned bit) {
    float v = fmaxf(E * Ev, e * e2);
    return bit ? v : 0.f;
}
__device__ __forceinline__ uint32_t packh2(float a, float b) {
    __half2 h = __floats2half2_rn(a, b);
    return *(uint32_t*)&h;
}

// ---------------- adjacency -> bitmask ----------------
__global__ void k_pack_mask(const int* __restrict__ adj) {
    int gw   = (blockIdx.x * blockDim.x + threadIdx.x) >> 5;
    int lane = threadIdx.x & 31;
    int v = adj[(size_t)gw * 32 + lane];
    unsigned m = __ballot_sync(0xffffffffu, v > 0);
    if (lane == 0) g_mask[gw] = m;
}

// ---------------- elementwise fp32 -> bf16 hi/lo split ----------------
__global__ void k_split_bf16(const float* __restrict__ in,
                             __nv_bfloat16* __restrict__ oh,
                             __nv_bfloat16* __restrict__ ol) {
    int idx = blockIdx.x * blockDim.x + threadIdx.x;
    float4 v = ((const float4*)in)[idx];
    __nv_bfloat162 h0 = __floats2bfloat162_rn(v.x, v.y);
    __nv_bfloat162 h1 = __floats2bfloat162_rn(v.z, v.w);
    __nv_bfloat162 l0 = __floats2bfloat162_rn(v.x - __bfloat162float(h0.x),
                                              v.y - __bfloat162float(h0.y));
    __nv_bfloat162 l1 = __floats2bfloat162_rn(v.z - __bfloat162float(h1.x),
                                              v.w - __bfloat162float(h1.y));
    ((__nv_bfloat162*)oh)[idx * 2] = h0;
    ((__nv_bfloat162*)oh)[idx * 2 + 1] = h1;
    ((__nv_bfloat162*)ol)[idx * 2] = l0;
    ((__nv_bfloat162*)ol)[idx * 2 + 1] = l1;
}

// ---------------- transpose fp32 [R,C] -> bf16 hi/lo [C,R] (GEMM weights) ----------------
__global__ void k_transpose_split(const float* __restrict__ in,
                                  __nv_bfloat16* __restrict__ oh,
                                  __nv_bfloat16* __restrict__ ol, int R, int C) {
    __shared__ float tile[32][33];
    int r0 = blockIdx.x * 32, c0 = blockIdx.y * 32;
    int tx = threadIdx.x, ty = threadIdx.y;
#pragma unroll
    for (int q = 0; q < 4; q++)
        tile[ty * 4 + q][tx] = in[(size_t)(r0 + ty * 4 + q) * C + c0 + tx];
    __syncthreads();
#pragma unroll
    for (int q = 0; q < 4; q++) {
        float v = tile[tx][ty * 4 + q];
        __nv_bfloat16 hi = __float2bfloat16(v);
        float lo = v - __bfloat162float(hi);
        size_t o = (size_t)(c0 + ty * 4 + q) * R + r0 + tx;
        oh[o] = hi;
        ol[o] = __float2bfloat16(lo);
    }
}

// ---------------- transpose fp32 [R,C] -> fp16 [C,R] (GAT h tiles) ----------------
__global__ void k_transpose_f16(const float* __restrict__ in,
                                __half* __restrict__ oh, int R, int C) {
    __shared__ float tile[32][33];
    int r0 = blockIdx.x * 32, c0 = blockIdx.y * 32;
    int tx = threadIdx.x, ty = threadIdx.y;
#pragma unroll
    for (int q = 0; q < 4; q++)
        tile[ty * 4 + q][tx] = in[(size_t)(r0 + ty * 4 + q) * C + c0 + tx];
    __syncthreads();
#pragma unroll
    for (int q = 0; q < 4; q++) {
        size_t o = (size_t)(c0 + ty * 4 + q) * R + r0 + tx;
        oh[o] = __float2half_rn(tile[tx][ty * 4 + q]);
    }
}

// ================ split-bf16 HMMA GEMM, 3-stage pipeline ================
template <int BN, int NWARP>
__device__ __forceinline__ void gemm_load(int t, int m0, int n0, int c, int buf,
                                          uint32_t sb, int K,
                                          const __nv_bfloat16* Ah, const __nv_bfloat16* Al,
                                          const __nv_bfloat16* Bh, const __nv_bfloat16* Bl) {
    constexpr int AB = 16384;
    constexpr int BB = BN * 128;
    constexpr int STAGE = 2 * AB + 2 * BB;
    uint32_t base = sb + buf * STAGE;
#pragma unroll
    for (int idx = t; idx < 1024; idx += NWARP * 32) {
        int m = idx >> 3, q = idx & 7;
        uint32_t off = base + (uint32_t)(m * 128 + ((q ^ (m & 7)) << 4));
        size_t src = (size_t)(m0 + m) * K + c * 64 + q * 8;
        cp16(off, Ah + src);
        cp16(off + AB, Al + src);
    }
#pragma unroll
    for (int idx = t; idx < BN * 8; idx += NWARP * 32) {
        int n = idx >> 3, q = idx & 7;
        uint32_t off = base + 2 * AB + (uint32_t)(n * 128 + ((q ^ (n & 7)) << 4));
        size_t src = (size_t)(n0 + n) * K + c * 64 + q * 8;
        cp16(off, Bh + src);
        cp16(off + BB, Bl + src);
    }
}

template <int BN, int NWARP>
__global__ __launch_bounds__(NWARP * 32) void k_gemm_hmma(
    const __nv_bfloat16* __restrict__ Ah, const __nv_bfloat16* __restrict__ Al,
    const __nv_bfloat16* __restrict__ Bh, const __nv_bfloat16* __restrict__ Bl,
    const float* __restrict__ bias, float* __restrict__ C, int K, int Ntot) {
    constexpr int AB = 16384;
    constexpr int BB = BN * 128;
    constexpr int STAGE = 2 * AB + 2 * BB;
    extern __shared__ char sm[];
    uint32_t sb = smem_u32(sm);
    int t = threadIdx.x, wid = t >> 5, lane = t & 31;
    int m0 = blockIdx.x * 128, n0 = blockIdx.y * BN;
    int wm = (wid & 3) * 32, wn = (wid >> 2) * 32;
    int g = lane >> 2, tig = lane & 3;
    int nc = K >> 6;

    int arow = (lane & 7) + ((lane >> 3) & 1) * 8;
    int ahalf = lane >> 4;
    int brow = ((lane >> 4) << 3) + (lane & 7);
    int bhalf = (lane >> 3) & 1;

    float acc[2][4][4];
#pragma unroll
    for (int mt = 0; mt < 2; mt++)
#pragma unroll
        for (int nt = 0; nt < 4; nt++)
#pragma unroll
            for (int q = 0; q < 4; q++) acc[mt][nt][q] = 0.f;

    gemm_load<BN, NWARP>(t, m0, n0, 0, 0, sb, K, Ah, Al, Bh, Bl);
    CP_COMMIT();
    if (nc > 1) gemm_load<BN, NWARP>(t, m0, n0, 1, 1, sb, K, Ah, Al, Bh, Bl);
    CP_COMMIT();

    for (int c = 0; c < nc; c++) {
        int buf = c % 3;
        CP_WAIT1();
        __syncthreads();
        if (c + 2 < nc)
            gemm_load<BN, NWARP>(t, m0, n0, c + 2, (c + 2) % 3, sb, K, Ah, Al, Bh, Bl);
        CP_COMMIT();
        uint32_t base = sb + buf * STAGE;
#pragma unroll
        for (int ks = 0; ks < 4; ks++) {
            uint32_t ahf[2][4], alf[2][4], bhf[2][4], blf[2][4];
#pragma unroll
            for (int mt = 0; mt < 2; mt++) {
                int r = wm + mt * 16 + arow;
                int slot = 2 * ks + ahalf;
                uint32_t ad = base + (uint32_t)(r * 128 + ((slot ^ (r & 7)) << 4));
                ldsm4(ahf[mt][0], ahf[mt][1], ahf[mt][2], ahf[mt][3], ad);
                ldsm4(alf[mt][0], alf[mt][1], alf[mt][2], alf[mt][3], ad + AB);
            }
#pragma unroll
            for (int np = 0; np < 2; np++) {
                int r = wn + np * 16 + brow;
                int slot = 2 * ks + bhalf;
                uint32_t bd = base + 2 * AB + (uint32_t)(r * 128 + ((slot ^ (r & 7)) << 4));
                ldsm4(bhf[np][0], bhf[np][1], bhf[np][2], bhf[np][3], bd);
                ldsm4(blf[np][0], blf[np][1], blf[np][2], blf[np][3], bd + BB);
            }
#pragma unroll
            for (int mt = 0; mt < 2; mt++)
#pragma unroll
                for (int nt = 0; nt < 4; nt++) {
                    int np = nt >> 1, sel = (nt & 1) * 2;
                    mma16816(acc[mt][nt], ahf[mt][0], ahf[mt][1], ahf[mt][2], ahf[mt][3],
                             bhf[np][sel], bhf[np][sel + 1]);
                }
#pragma unroll
            for (int mt = 0; mt < 2; mt++)
#pragma unroll
                for (int nt = 0; nt < 4; nt++) {
                    int np = nt >> 1, sel = (nt & 1) * 2;
                    mma16816(acc[mt][nt], ahf[mt][0], ahf[mt][1], ahf[mt][2], ahf[mt][3],
                             blf[np][sel], blf[np][sel + 1]);
                }
#pragma unroll
            for (int mt = 0; mt < 2; mt++)
#pragma unroll
                for (int nt = 0; nt < 4; nt++) {
                    int np = nt >> 1, sel = (nt & 1) * 2;
                    mma16816(acc[mt][nt], alf[mt][0], alf[mt][1], alf[mt][2], alf[mt][3],
                             bhf[np][sel], bhf[np][sel + 1]);
                }
        }
    }
#pragma unroll
    for (int mt = 0; mt < 2; mt++)
#pragma unroll
        for (int nt = 0; nt < 4; nt++) {
            int row = m0 + wm + mt * 16 + g;
            int col = n0 + wn + nt * 8 + tig * 2;
            float bv0 = bias ? bias[col] : 0.f;
            float bv1 = bias ? bias[col + 1] : 0.f;
            float2 v0 = make_float2(acc[mt][nt][0] + bv0, acc[mt][nt][1] + bv1);
            float2 v1 = make_float2(acc[mt][nt][2] + bv0, acc[mt][nt][3] + bv1);
            *(float2*)&C[(size_t)row * Ntot + col] = v0;
            *(float2*)&C[(size_t)(row + 8) * Ntot + col] = v1;
        }
}

// ---------------- fp32 GEMM for lin2 ----------------
template <int BM, int BN, int BK, int TM, int TN>
__global__ void k_gemm_bias(const float* __restrict__ A, const float* __restrict__ B,
                            const float* __restrict__ bias, float* __restrict__ C,
                            int M, int Nn, int K) {
    constexpr int THREADS = (BM / TM) * (BN / TN);
    __shared__ float As[BM][BK + 1];
    __shared__ float Bs[BK][BN + 1];
    int tid = threadIdx.x;
    int rm = tid / (BN / TN);
    int rn = tid % (BN / TN);
    int m0 = blockIdx.y * BM, n0 = blockIdx.x * BN;
    float acc[TM][TN];
#pragma unroll
    for (int m = 0; m < TM; m++)
#pragma unroll
        for (int n = 0; n < TN; n++) acc[m][n] = 0.f;

    for (int k0 = 0; k0 < K; k0 += BK) {
        for (int idx = tid; idx < BM * BK; idx += THREADS) {
            int r = idx / BK, c = idx % BK;
            As[r][c] = A[(size_t)(m0 + r) * K + k0 + c];
        }
        for (int idx = tid; idx < BK * BN; idx += THREADS) {
            int r = idx / BN, c = idx % BN;
            Bs[r][c] = B[(size_t)(k0 + r) * Nn + n0 + c];
        }
        __syncthreads();
#pragma unroll
        for (int kk = 0; kk < BK; kk++) {
            float a[TM], b[TN];
#pragma unroll
            for (int m = 0; m < TM; m++) a[m] = As[rm * TM + m][kk];
#pragma unroll
            for (int n = 0; n < TN; n++) b[n] = Bs[kk][rn * TN + n];
#pragma unroll
            for (int m = 0; m < TM; m++)
#pragma unroll
                for (int n = 0; n < TN; n++) acc[m][n] = fmaf(a[m], b[n], acc[m][n]);
        }
        __syncthreads();
    }
#pragma unroll
    for (int m = 0; m < TM; m++) {
        int row = m0 + rm * TM + m;
#pragma unroll
        for (int n = 0; n < TN; n++) {
            int col = n0 + rn * TN + n;
            float v = acc[m][n];
            if (bias) v += bias[col];
            C[(size_t)row * Nn + col] = v;
        }
    }
}

// ---------------- per-node scores + precomputed exps ----------------
template <int F>
__global__ void k_attn_scores(const float* __restrict__ hfeat,
                              const float* __restrict__ a_src,
                              const float* __restrict__ a_dst,
                              float* __restrict__ sc) {
    int n = blockIdx.x * (blockDim.x >> 5) + (threadIdx.x >> 5);
    int lane = threadIdx.x & 31;
    if (n >= NN) return;
    const float* row = hfeat + (size_t)n * (H * F);
#pragma unroll
    for (int h = 0; h < H; h++) {
        float ss = 0.f, sd = 0.f;
        for (int k = lane; k < F; k += 32) {
            float v = row[h * F + k];
            ss = fmaf(v, a_src[h * F + k], ss);
            sd = fmaf(v, a_dst[h * F + k], sd);
        }
#pragma unroll
        for (int o = 16; o; o >>= 1) {
            ss += __shfl_xor_sync(0xffffffffu, ss, o);
            sd += __shfl_xor_sync(0xffffffffu, sd, o);
        }
        if (lane == 0) {
            int idx = h * NN + n;
            sc[0 * HN + idx] = ss;
            sc[1 * HN + idx] = expf(ss);
            sc[2 * HN + idx] = expf(LRELU * ss);
            sc[3 * HN + idx] = sd;
            sc[4 * HN + idx] = expf(sd);
            sc[5 * HN + idx] = expf(LRELU * sd);
        }
    }
}

// ================ GAT aggregation: fp16 A x fp16 B (single plane), ones-col denominator ================
template <int F>
__device__ __forceinline__ void load_chunk(int t, int head, int i0, int c, int buf,
                                           char* BtB, unsigned* mk, float* edb,
                                           const __half* hTh, const float* sc) {
    constexpr int BT = F * 128;
    char* dst = BtB + buf * BT;
    for (int idx = t; idx < F * 8; idx += 256) {
        int f = idx >> 3, q = idx & 7;
        uint32_t off = (uint32_t)(f * 128 + (((q ^ (f & 7)) << 4)));
        cp16(smem_u32(dst + off), hTh + (size_t)(head * F + f) * NN + c * 64 + q * 8);
    }
    if (t < 128) cp8(smem_u32(mk + buf * 256 + t * 2), &g_mask[(size_t)(i0 + t) * NW + c * 2]);
    if (t < 32) {
        int a = t >> 4, q = t & 15;
        cp16(smem_u32(edb + buf * 128 + a * 64 + q * 4),
             &sc[(size_t)(4 + a) * HN + head * NN + c * 64 + q * 4]);
    }
}

template <int F>
__global__ __launch_bounds__(256) void k_gat_hmma(const __half* __restrict__ hTh,
                                                  const float* __restrict__ sc,
                                                  float* __restrict__ part,
                                                  float* __restrict__ dp) {
    constexpr int BT = F * 128;
    constexpr int MPF = F / 16;
    constexpr uint32_t ONES = 0x3C003C00u;  // fp16 (1.0, 1.0)
    extern __shared__ char smem[];
    char* BtB = smem;                               // [3][BT]
    unsigned* mk = (unsigned*)(smem + 3 * BT);      // [3][256]
    float* edb = (float*)(smem + 3 * BT + 3072);    // [3][128]

    int t = threadIdx.x, wid = t >> 5, lane = t & 31;
    int g = lane >> 2, tig = lane & 3;
    int head = blockIdx.y, i0 = blockIdx.x * 128;
    int z = blockIdx.z;
    int c0 = z * 32;
    uint32_t sb = smem_u32(smem);

    int r0 = wid * 16 + g, r1 = r0 + 8;
    const float* scb = sc + head * NN + i0;
    float E0 = scb[HN + r0], e0 = scb[2 * HN + r0];
    float E1 = scb[HN + r1], e1 = scb[2 * HN + r1];

    int flr = ((lane >> 4) & 1) * 8 + (lane & 7);
    int qb = (lane >> 3) & 1;
    int sxw = flr & 7;
    uint32_t fcol = (uint32_t)(flr * 128);

    float acc[2 * MPF][4];
#pragma unroll
    for (int nt = 0; nt < 2 * MPF; nt++)
#pragma unroll
        for (int q = 0; q < 4; q++) acc[nt][q] = 0.f;
    float accd[4] = {0.f, 0.f, 0.f, 0.f};

    load_chunk<F>(t, head, i0, c0, 0, BtB, mk, edb, hTh, sc);
    CP_COMMIT();
    load_chunk<F>(t, head, i0, c0 + 1, 1, BtB, mk, edb, hTh, sc);
    CP_COMMIT();

    for (int cc = 0; cc < 32; cc++) {
        int b = cc % 3;
        CP_WAIT1();
        __syncthreads();
        if (cc < 30)
            load_chunk<F>(t, head, i0, c0 + cc + 2, (cc + 2) % 3, BtB, mk, edb, hTh, sc);
        CP_COMMIT();
        unsigned* mkb = mk + b * 256;
        unsigned m0a = mkb[r0 * 2], m0b = mkb[r0 * 2 + 1];
        unsigned m1a = mkb[r1 * 2], m1b = mkb[r1 * 2 + 1];
        float* ed = edb + b * 128;
        uint32_t bufbase = sb + (uint32_t)(b * BT);
#pragma unroll
        for (int ks = 0; ks < 4; ks++) {
            int jb = ks * 16 + tig * 2;
            float2 EvL = *(float2*)&ed[jb];
            float2 EvH = *(float2*)&ed[jb + 8];
            float2 e2L = *(float2*)&ed[64 + jb];
            float2 e2H = *(float2*)&ed[64 + jb + 8];
            int bit = (ks & 1) * 16 + tig * 2;
            unsigned w0 = (ks < 2) ? m0a : m0b;
            unsigned w1 = (ks < 2) ? m1a : m1b;

            float a0 = wmax(E0, e0, EvL.x, e2L.x, (w0 >> bit) & 1u);
            float a1 = wmax(E0, e0, EvL.y, e2L.y, (w0 >> (bit + 1)) & 1u);
            float a2 = wmax(E0, e0, EvH.x, e2H.x, (w0 >> (bit + 8)) & 1u);
            float a3 = wmax(E0, e0, EvH.y, e2H.y, (w0 >> (bit + 9)) & 1u);
            float b0 = wmax(E1, e1, EvL.x, e2L.x, (w1 >> bit) & 1u);
            float b1 = wmax(E1, e1, EvL.y, e2L.y, (w1 >> (bit + 1)) & 1u);
            float b2 = wmax(E1, e1, EvH.x, e2H.x, (w1 >> (bit + 8)) & 1u);
            float b3 = wmax(E1, e1, EvH.y, e2H.y, (w1 >> (bit + 9)) & 1u);
            uint32_t A0 = packh2(a0, a1);
            uint32_t A1 = packh2(b0, b1);
            uint32_t A2 = packh2(a2, a3);
            uint32_t A3 = packh2(b2, b3);

            // denominator: ones-column MMA (d_i = sum_j w_ij)
            mma16816h(accd, A0, A1, A2, A3, ONES, ONES);

            uint32_t swz = (uint32_t)((((2 * ks + qb) ^ sxw) << 4));
#pragma unroll
            for (int mp = 0; mp < MPF; mp++) {
                uint32_t ad = bufbase + fcol + (uint32_t)(mp * 2048) + swz;
                uint32_t bh0, bh1, bh2, bh3;
                ldsm4(bh0, bh1, bh2, bh3, ad);
                mma16816h(acc[2 * mp],     A0, A1, A2, A3, bh0, bh1);
                mma16816h(acc[2 * mp + 1], A0, A1, A2, A3, bh2, bh3);
            }
        }
    }
    if (tig == 0) {
        dp[(size_t)z * HN + head * NN + i0 + r0] = accd[0];
        dp[(size_t)z * HN + head * NN + i0 + r1] = accd[2];
    }
    float* pz = part + (size_t)z * NN * (H * F);
#pragma unroll
    for (int nt = 0; nt < 2 * MPF; nt++) {
        int col = head * F + nt * 8 + tig * 2;
        *(float2*)&pz[(size_t)(i0 + r0) * (H * F) + col] = make_float2(acc[nt][0], acc[nt][1]);
        *(float2*)&pz[(size_t)(i0 + r1) * (H * F) + col] = make_float2(acc[nt][2], acc[nt][3]);
    }
}

// ---- combine K-split partials, normalize, optional bf16 split output ----
template <int F, bool SPLIT>
__global__ void k_gat_fin(const float* __restrict__ part, const float* __restrict__ dp,
                          float* __restrict__ out,
                          __nv_bfloat16* __restrict__ oh, __nv_bfloat16* __restrict__ ol) {
    constexpr int HF = H * F;
    int idx = blockIdx.x * blockDim.x + threadIdx.x;
    int e0 = idx * 4;
    int row = e0 / HF, cc = e0 % HF, head = cc / F;
    float inv = 1.f / (dp[head * NN + row] + dp[HN + head * NN + row]);
    float4 p0 = ((const float4*)part)[idx];
    float4 p1 = ((const float4*)(part + (size_t)NN * HF))[idx];
    float v0 = (p0.x + p1.x) * inv, v1 = (p0.y + p1.y) * inv;
    float v2 = (p0.z + p1.z) * inv, v3 = (p0.w + p1.w) * inv;
    if (SPLIT) {
        __nv_bfloat162 h0 = __floats2bfloat162_rn(v0, v1);
        __nv_bfloat162 h1 = __floats2bfloat162_rn(v2, v3);
        __nv_bfloat162 l0 = __floats2bfloat162_rn(v0 - __bfloat162float(h0.x),
                                                  v1 - __bfloat162float(h0.y));
        __nv_bfloat162 l1 = __floats2bfloat162_rn(v2 - __bfloat162float(h1.x),
                                                  v3 - __bfloat162float(h1.y));
        ((__nv_bfloat162*)oh)[idx * 2] = h0;
        ((__nv_bfloat162*)oh)[idx * 2 + 1] = h1;
        ((__nv_bfloat162*)ol)[idx * 2] = l0;
        ((__nv_bfloat162*)ol)[idx * 2 + 1] = l1;
    } else {
        ((float4*)out)[idx] = make_float4(v0, v1, v2, v3);
    }
}

// ---------------- batchnorm ----------------
template <int C>
__global__ void k_bn_part(const float* __restrict__ z, float* __restrict__ part) {
    constexpr int RL = 256 / C;
    int blk = blockIdx.x;
    int t = threadIdx.x;
    int col = t % C, rl = t / C;
    float s = 0.f, s2 = 0.f;
    for (int r = rl; r < 128; r += RL) {
        float v = z[(size_t)(blk * 128 + r) * C + col];
        s += v; s2 += v * v;
    }
    __shared__ float sh[256], sh2[256];
    sh[t] = s; sh2[t] = s2;
    __syncthreads();
    if (rl == 0) {
#pragma unroll
        for (int q = 1; q < RL; q++) { s += sh[q * C + col]; s2 += sh2[q * C + col]; }
        part[blk * 2 * C + col] = s;
        part[blk * 2 * C + C + col] = s2;
    }
}
template <int C>
__global__ void k_bn_fin(const float* __restrict__ part,
                         float* __restrict__ mean, float* __restrict__ rstd) {
    int c = threadIdx.x;
    if (c >= C) return;
    double s = 0.0, s2 = 0.0;
    for (int b = 0; b < 32; b++) { s += part[b * 2 * C + c]; s2 += part[b * 2 * C + C + c]; }
    double mu = s / NN;
    double var = s2 / NN - mu * mu;
    mean[c] = (float)mu;
    rstd[c] = rsqrtf((float)var + BN_EPS);
}

__global__ void k_bn_elu(const float* __restrict__ z, const float* __restrict__ mean,
                         const float* __restrict__ rstd, const float* __restrict__ gamma,
                         const float* __restrict__ beta, float* __restrict__ out, int C) {
    int idx = blockIdx.x * blockDim.x + threadIdx.x;
    int c = idx % C;
    float v = (z[idx] - mean[c]) * rstd[c] * gamma[c] + beta[c];
    out[idx] = v > 0.f ? v : (expf(v) - 1.f);
}

__global__ void k_bn_elu_split(const float* __restrict__ z, const float* __restrict__ mean,
                               const float* __restrict__ rstd, const float* __restrict__ gamma,
                               const float* __restrict__ beta,
                               __nv_bfloat16* __restrict__ oh, __nv_bfloat16* __restrict__ ol,
                               int C) {
    int idx = blockIdx.x * blockDim.x + threadIdx.x;
    int c = idx % C;
    float v = (z[idx] - mean[c]) * rstd[c] * gamma[c] + beta[c];
    v = v > 0.f ? v : (expf(v) - 1.f);
    __nv_bfloat16 hi = __float2bfloat16(v);
    oh[idx] = hi;
    ol[idx] = __float2bfloat16(v - __bfloat162float(hi));
}

// ---------------- launch ----------------
extern "C" void kernel_launch(void* const* d_in, const int* in_sizes, int n_in,
                              void* d_out, int out_size) {
    const float* x   = (const float*)d_in[0];
    const int*   adj = (const int*)d_in[1];
    const float* W1  = (const float*)d_in[2];
    const float* a1s = (const float*)d_in[3];
    const float* a1d = (const float*)d_in[4];
    const float* lw1 = (const float*)d_in[5];
    const float* lb1 = (const float*)d_in[6];
    const float* g1  = (const float*)d_in[7];
    const float* be1 = (const float*)d_in[8];
    const float* W2  = (const float*)d_in[9];
    const float* a2s = (const float*)d_in[10];
    const float* a2d = (const float*)d_in[11];
    const float* lw2 = (const float*)d_in[12];
    const float* lb2 = (const float*)d_in[13];
    const float* g2  = (const float*)d_in[14];
    const float* be2 = (const float*)d_in[15];
    float* out = (float*)d_out;

    float *h1, *x2, *h2, *x3, *z4, *sc1, *sc2, *mean, *rstd, *bnp, *part, *dp;
    __half *h1th, *h2th;
    __nv_bfloat16 *ah, *al, *wth, *wtl, *lw1th, *lw1tl, *w2th, *w2tl;
    cudaGetSymbolAddress((void**)&h1, g_h1);
    cudaGetSymbolAddress((void**)&x2, g_x2);
    cudaGetSymbolAddress((void**)&h2, g_h2);
    cudaGetSymbolAddress((void**)&x3, g_x3);
    cudaGetSymbolAddress((void**)&z4, g_z4);
    cudaGetSymbolAddress((void**)&sc1, g_sc1);
    cudaGetSymbolAddress((void**)&sc2, g_sc2);
    cudaGetSymbolAddress((void**)&mean, g_mean);
    cudaGetSymbolAddress((void**)&rstd, g_rstd);
    cudaGetSymbolAddress((void**)&bnp, g_bnpart);
    cudaGetSymbolAddress((void**)&part, g_part);
    cudaGetSymbolAddress((void**)&dp, g_dp);
    cudaGetSymbolAddress((void**)&h1th, g_h1th);
    cudaGetSymbolAddress((void**)&h2th, g_h2th);
    cudaGetSymbolAddress((void**)&ah, g_ah);
    cudaGetSymbolAddress((void**)&al, g_al);
    cudaGetSymbolAddress((void**)&wth, g_wth);
    cudaGetSymbolAddress((void**)&wtl, g_wtl);
    cudaGetSymbolAddress((void**)&lw1th, g_lw1th);
    cudaGetSymbolAddress((void**)&lw1tl, g_lw1tl);
    cudaGetSymbolAddress((void**)&w2th, g_w2th);
    cudaGetSymbolAddress((void**)&w2tl, g_w2tl);

    const int SMEM1 = 3 * F1 * 128 + 3072 + 1536;   // ~53 KB
    const int SMEM2 = 3 * F2 * 128 + 3072 + 1536;   // ~17 KB
    const int SMEMG128 = 3 * (2 * 16384 + 2 * 128 * 128);
    const int SMEMG64  = 3 * (2 * 16384 + 2 * 64 * 128);
    cudaFuncSetAttribute((const void*)k_gat_hmma<F1>,
                         cudaFuncAttributeMaxDynamicSharedMemorySize, SMEM1);
    cudaFuncSetAttribute((const void*)k_gat_hmma<F2>,
                         cudaFuncAttributeMaxDynamicSharedMemorySize, SMEM2);
    cudaFuncSetAttribute((const void*)k_gemm_hmma<128, 16>,
                         cudaFuncAttributeMaxDynamicSharedMemorySize, SMEMG128);
    cudaFuncSetAttribute((const void*)k_gemm_hmma<64, 8>,
                         cudaFuncAttributeMaxDynamicSharedMemorySize, SMEMG64);

    static cudaStream_t s2 = nullptr;
    static cudaEvent_t e0 = nullptr, e2 = nullptr, e3 = nullptr, e4 = nullptr, e5 = nullptr;
    if (!s2) {
        cudaStreamCreateWithFlags(&s2, cudaStreamNonBlocking);
        cudaEventCreateWithFlags(&e0, cudaEventDisableTiming);
        cudaEventCreateWithFlags(&e2, cudaEventDisableTiming);
        cudaEventCreateWithFlags(&e3, cudaEventDisableTiming);
        cudaEventCreateWithFlags(&e4, cudaEventDisableTiming);
        cudaEventCreateWithFlags(&e5, cudaEventDisableTiming);
    }

    cudaEventRecord(e0, 0);
    cudaStreamWaitEvent(s2, e0, 0);
    k_pack_mask<<<(NN * NN) / 256, 256, 0, s2>>>(adj);
    k_transpose_split<<<dim3(512 / 32, HID1 / 32), dim3(32, 8), 0, s2>>>(lw1, lw1th, lw1tl, 512, HID1);
    k_transpose_split<<<dim3(HID1 / 32, 128 / 32), dim3(32, 8), 0, s2>>>(W2, w2th, w2tl, HID1, 128);

    k_split_bf16<<<(NN * IN_F / 4) / 256, 256>>>(x, ah, al);
    k_transpose_split<<<dim3(IN_F / 32, 512 / 32), dim3(32, 8)>>>(W1, wth, wtl, IN_F, 512);
    k_gemm_hmma<128, 16><<<dim3(NN / 128, 512 / 128), 512, SMEMG128>>>(
        ah, al, wth, wtl, nullptr, h1, IN_F, 512);

    cudaEventRecord(e2, 0);
    cudaStreamWaitEvent(s2, e2, 0);
    k_transpose_f16<<<dim3(NN / 32, 512 / 32), dim3(32, 8), 0, s2>>>(h1, h1th, NN, 512);
    k_attn_scores<F1><<<NN / 8, 256>>>(h1, a1s, a1d, sc1);
    cudaEventRecord(e3, s2);
    cudaStreamWaitEvent(0, e3, 0);

    k_gat_hmma<F1><<<dim3(NN / 128, H, 2), 256, SMEM1>>>(h1th, sc1, part, dp);
    k_gat_fin<F1, true><<<(NN * 512 / 4) / 256, 256>>>(part, dp, nullptr, ah, al);

    k_gemm_hmma<64, 8><<<dim3(NN / 128, HID1 / 64), 256, SMEMG64>>>(
        ah, al, lw1th, lw1tl, lb1, x2, 512, HID1);

    k_bn_part<HID1><<<32, 256>>>(x2, bnp);
    k_bn_fin<HID1><<<1, 64>>>(bnp, mean, rstd);
    k_bn_elu_split<<<(NN * HID1) / 256, 256>>>(x2, mean, rstd, g1, be1, ah, al, HID1);

    k_gemm_hmma<128, 16><<<dim3(NN / 128, 1), 512, SMEMG128>>>(
        ah, al, w2th, w2tl, nullptr, h2, HID1, 128);

    cudaEventRecord(e4, 0);
    cudaStreamWaitEvent(s2, e4, 0);
    k_transpose_f16<<<dim3(NN / 32, 128 / 32), dim3(32, 8), 0, s2>>>(h2, h2th, NN, 128);
    k_attn_scores<F2><<<NN / 8, 256>>>(h2, a2s, a2d, sc2);
    cudaEventRecord(e5, s2);
    cudaStreamWaitEvent(0, e5, 0);

    k_gat_hmma<F2><<<dim3(NN / 128, H, 2), 256, SMEM2>>>(h2th, sc2, part, dp);
    k_gat_fin<F2, false><<<(NN * 128 / 4) / 256, 256>>>(part, dp, x3, nullptr, nullptr);

    k_gemm_bias<128, 16, 32, 4, 2><<<dim3(1, NN / 128), 256>>>(x3, lw2, lb2, z4, NN, OUT_F, 128);

    k_bn_part<OUT_F><<<32, 256>>>(z4, bnp);
    k_bn_fin<OUT_F><<<1, 64>>>(bnp, mean, rstd);
    k_bn_elu<<<(NN * OUT_F) / 256, 256>>>(z4, mean, rstd, g2, be2, out, OUT_F);
}

// round 16
// speedup vs baseline: 1.4790x; 1.0672x over previous
#include <cuda_runtime.h>
#include <cuda_bf16.h>
#include <cuda_fp16.h>
#include <math.h>
#include <stdint.h>

#define NN 4096
#define NW 128
#define H 4
#define F1 128
#define F2 32
#define HN (H * NN)
#define IN_F 512
#define HID1 64
#define OUT_F 16
#define LRELU 0.2f
#define BN_EPS 1e-5f

// ---------------- scratch ----------------
__device__ float         g_h1[NN * 512];
__device__ float         g_x2[NN * HID1];
__device__ float         g_h2[NN * 128];
__device__ float         g_x3[NN * 128];
__device__ float         g_z4[NN * OUT_F];
__device__ float         g_sc1[6 * HN];
__device__ float         g_sc2[6 * HN];
__device__ __half        g_sch1[2 * HN];     // fp16 j-side: [0]=exp(ed), [1]=exp(.2ed)
__device__ __half        g_sch2[2 * HN];
__device__ unsigned      g_mask[NN * NW];
__device__ float         g_mean[64], g_rstd[64];
__device__ float         g_bnpart[32 * 2 * 64];
__device__ float         g_part[2 * NN * 512];
__device__ float         g_dp[2 * HN];
__device__ __half        g_h1th[512 * NN];   // h1^T fp16
__device__ __half        g_h2th[128 * NN];   // h2^T fp16
__device__ __nv_bfloat16 g_ah[NN * 512];
__device__ __nv_bfloat16 g_al[NN * 512];
__device__ __nv_bfloat16 g_wth[512 * 512];
__device__ __nv_bfloat16 g_wtl[512 * 512];
__device__ __nv_bfloat16 g_lw1th[HID1 * 512];
__device__ __nv_bfloat16 g_lw1tl[HID1 * 512];
__device__ __nv_bfloat16 g_w2th[128 * HID1];
__device__ __nv_bfloat16 g_w2tl[128 * HID1];

// ================= helpers =================
__device__ __forceinline__ uint32_t smem_u32(const void* p) {
    uint32_t a;
    asm("{ .reg .u64 t; cvta.to.shared.u64 t, %1; cvt.u32.u64 %0, t; }" : "=r"(a) : "l"(p));
    return a;
}
__device__ __forceinline__ void cp16(uint32_t dst, const void* src) {
    asm volatile("cp.async.cg.shared.global [%0], [%1], 16;" :: "r"(dst), "l"(src));
}
__device__ __forceinline__ void cp8(uint32_t dst, const void* src) {
    asm volatile("cp.async.ca.shared.global [%0], [%1], 8;" :: "r"(dst), "l"(src));
}
#define CP_COMMIT() asm volatile("cp.async.commit_group;" ::: "memory")
#define CP_WAIT1()  asm volatile("cp.async.wait_group 1;" ::: "memory")

__device__ __forceinline__ void mma16816(float* c,
    uint32_t a0, uint32_t a1, uint32_t a2, uint32_t a3, uint32_t b0, uint32_t b1) {
    asm volatile(
        "mma.sync.aligned.m16n8k16.row.col.f32.bf16.bf16.f32 "
        "{%0,%1,%2,%3}, {%4,%5,%6,%7}, {%8,%9}, {%0,%1,%2,%3};"
        : "+f"(c[0]), "+f"(c[1]), "+f"(c[2]), "+f"(c[3])
        : "r"(a0), "r"(a1), "r"(a2), "r"(a3), "r"(b0), "r"(b1));
}
__device__ __forceinline__ void mma16816h(float* c,
    uint32_t a0, uint32_t a1, uint32_t a2, uint32_t a3, uint32_t b0, uint32_t b1) {
    asm volatile(
        "mma.sync.aligned.m16n8k16.row.col.f32.f16.f16.f32 "
        "{%0,%1,%2,%3}, {%4,%5,%6,%7}, {%8,%9}, {%0,%1,%2,%3};"
        : "+f"(c[0]), "+f"(c[1]), "+f"(c[2]), "+f"(c[3])
        : "r"(a0), "r"(a1), "r"(a2), "r"(a3), "r"(b0), "r"(b1));
}
__device__ __forceinline__ void ldsm4(uint32_t& r0, uint32_t& r1, uint32_t& r2, uint32_t& r3,
                                      uint32_t addr) {
    asm volatile("ldmatrix.sync.aligned.m8n8.x4.shared.b16 {%0,%1,%2,%3}, [%4];"
                 : "=r"(r0), "=r"(r1), "=r"(r2), "=r"(r3) : "r"(addr));
}
// half2 weight-gen: max(E*Ev, e*e2) masked by 2 adjacency bits
__device__ __forceinline__ uint32_t wgen2(__half2 Eh, __half2 eh, __half2 Ev, __half2 e2,
                                          unsigned w, int bit) {
    __half2 v = __hmax2(__hmul2(Eh, Ev), __hmul2(eh, e2));
    uint32_t u = *(uint32_t*)&v;
    uint32_t lo = ((w >> bit) & 1u) ? 0x0000FFFFu : 0u;
    uint32_t hi = ((w >> (bit + 1)) & 1u) ? 0xFFFF0000u : 0u;
    return u & (lo | hi);
}

// ---------------- adjacency -> bitmask ----------------
__global__ void k_pack_mask(const int* __restrict__ adj) {
    int gw   = (blockIdx.x * blockDim.x + threadIdx.x) >> 5;
    int lane = threadIdx.x & 31;
    int v = adj[(size_t)gw * 32 + lane];
    unsigned m = __ballot_sync(0xffffffffu, v > 0);
    if (lane == 0) g_mask[gw] = m;
}

// ---------------- elementwise fp32 -> bf16 hi/lo split ----------------
__global__ void k_split_bf16(const float* __restrict__ in,
                             __nv_bfloat16* __restrict__ oh,
                             __nv_bfloat16* __restrict__ ol) {
    int idx = blockIdx.x * blockDim.x + threadIdx.x;
    float4 v = ((const float4*)in)[idx];
    __nv_bfloat162 h0 = __floats2bfloat162_rn(v.x, v.y);
    __nv_bfloat162 h1 = __floats2bfloat162_rn(v.z, v.w);
    __nv_bfloat162 l0 = __floats2bfloat162_rn(v.x - __bfloat162float(h0.x),
                                              v.y - __bfloat162float(h0.y));
    __nv_bfloat162 l1 = __floats2bfloat162_rn(v.z - __bfloat162float(h1.x),
                                              v.w - __bfloat162float(h1.y));
    ((__nv_bfloat162*)oh)[idx * 2] = h0;
    ((__nv_bfloat162*)oh)[idx * 2 + 1] = h1;
    ((__nv_bfloat162*)ol)[idx * 2] = l0;
    ((__nv_bfloat162*)ol)[idx * 2 + 1] = l1;
}

// ---------------- transpose fp32 [R,C] -> bf16 hi/lo [C,R] (GEMM weights) ----------------
__global__ void k_transpose_split(const float* __restrict__ in,
                                  __nv_bfloat16* __restrict__ oh,
                                  __nv_bfloat16* __restrict__ ol, int R, int C) {
    __shared__ float tile[32][33];
    int r0 = blockIdx.x * 32, c0 = blockIdx.y * 32;
    int tx = threadIdx.x, ty = threadIdx.y;
#pragma unroll
    for (int q = 0; q < 4; q++)
        tile[ty * 4 + q][tx] = in[(size_t)(r0 + ty * 4 + q) * C + c0 + tx];
    __syncthreads();
#pragma unroll
    for (int q = 0; q < 4; q++) {
        float v = tile[tx][ty * 4 + q];
        __nv_bfloat16 hi = __float2bfloat16(v);
        float lo = v - __bfloat162float(hi);
        size_t o = (size_t)(c0 + ty * 4 + q) * R + r0 + tx;
        oh[o] = hi;
        ol[o] = __float2bfloat16(lo);
    }
}

// ---------------- transpose fp32 [R,C] -> fp16 [C,R] (GAT h tiles) ----------------
__global__ void k_transpose_f16(const float* __restrict__ in,
                                __half* __restrict__ oh, int R, int C) {
    __shared__ float tile[32][33];
    int r0 = blockIdx.x * 32, c0 = blockIdx.y * 32;
    int tx = threadIdx.x, ty = threadIdx.y;
#pragma unroll
    for (int q = 0; q < 4; q++)
        tile[ty * 4 + q][tx] = in[(size_t)(r0 + ty * 4 + q) * C + c0 + tx];
    __syncthreads();
#pragma unroll
    for (int q = 0; q < 4; q++) {
        size_t o = (size_t)(c0 + ty * 4 + q) * R + r0 + tx;
        oh[o] = __float2half_rn(tile[tx][ty * 4 + q]);
    }
}

// ================ split-bf16 HMMA GEMM, 3-stage pipeline ================
template <int BN, int NWARP>
__device__ __forceinline__ void gemm_load(int t, int m0, int n0, int c, int buf,
                                          uint32_t sb, int K,
                                          const __nv_bfloat16* Ah, const __nv_bfloat16* Al,
                                          const __nv_bfloat16* Bh, const __nv_bfloat16* Bl) {
    constexpr int AB = 16384;
    constexpr int BB = BN * 128;
    constexpr int STAGE = 2 * AB + 2 * BB;
    uint32_t base = sb + buf * STAGE;
#pragma unroll
    for (int idx = t; idx < 1024; idx += NWARP * 32) {
        int m = idx >> 3, q = idx & 7;
        uint32_t off = base + (uint32_t)(m * 128 + ((q ^ (m & 7)) << 4));
        size_t src = (size_t)(m0 + m) * K + c * 64 + q * 8;
        cp16(off, Ah + src);
        cp16(off + AB, Al + src);
    }
#pragma unroll
    for (int idx = t; idx < BN * 8; idx += NWARP * 32) {
        int n = idx >> 3, q = idx & 7;
        uint32_t off = base + 2 * AB + (uint32_t)(n * 128 + ((q ^ (n & 7)) << 4));
        size_t src = (size_t)(n0 + n) * K + c * 64 + q * 8;
        cp16(off, Bh + src);
        cp16(off + BB, Bl + src);
    }
}

template <int BN, int NWARP>
__global__ __launch_bounds__(NWARP * 32) void k_gemm_hmma(
    const __nv_bfloat16* __restrict__ Ah, const __nv_bfloat16* __restrict__ Al,
    const __nv_bfloat16* __restrict__ Bh, const __nv_bfloat16* __restrict__ Bl,
    const float* __restrict__ bias, float* __restrict__ C, int K, int Ntot) {
    constexpr int AB = 16384;
    constexpr int BB = BN * 128;
    constexpr int STAGE = 2 * AB + 2 * BB;
    extern __shared__ char sm[];
    uint32_t sb = smem_u32(sm);
    int t = threadIdx.x, wid = t >> 5, lane = t & 31;
    int m0 = blockIdx.x * 128, n0 = blockIdx.y * BN;
    int wm = (wid & 3) * 32, wn = (wid >> 2) * 32;
    int g = lane >> 2, tig = lane & 3;
    int nc = K >> 6;

    int arow = (lane & 7) + ((lane >> 3) & 1) * 8;
    int ahalf = lane >> 4;
    int brow = ((lane >> 4) << 3) + (lane & 7);
    int bhalf = (lane >> 3) & 1;

    float acc[2][4][4];
#pragma unroll
    for (int mt = 0; mt < 2; mt++)
#pragma unroll
        for (int nt = 0; nt < 4; nt++)
#pragma unroll
            for (int q = 0; q < 4; q++) acc[mt][nt][q] = 0.f;

    gemm_load<BN, NWARP>(t, m0, n0, 0, 0, sb, K, Ah, Al, Bh, Bl);
    CP_COMMIT();
    if (nc > 1) gemm_load<BN, NWARP>(t, m0, n0, 1, 1, sb, K, Ah, Al, Bh, Bl);
    CP_COMMIT();

    for (int c = 0; c < nc; c++) {
        int buf = c % 3;
        CP_WAIT1();
        __syncthreads();
        if (c + 2 < nc)
            gemm_load<BN, NWARP>(t, m0, n0, c + 2, (c + 2) % 3, sb, K, Ah, Al, Bh, Bl);
        CP_COMMIT();
        uint32_t base = sb + buf * STAGE;
#pragma unroll
        for (int ks = 0; ks < 4; ks++) {
            uint32_t ahf[2][4], alf[2][4], bhf[2][4], blf[2][4];
#pragma unroll
            for (int mt = 0; mt < 2; mt++) {
                int r = wm + mt * 16 + arow;
                int slot = 2 * ks + ahalf;
                uint32_t ad = base + (uint32_t)(r * 128 + ((slot ^ (r & 7)) << 4));
                ldsm4(ahf[mt][0], ahf[mt][1], ahf[mt][2], ahf[mt][3], ad);
                ldsm4(alf[mt][0], alf[mt][1], alf[mt][2], alf[mt][3], ad + AB);
            }
#pragma unroll
            for (int np = 0; np < 2; np++) {
                int r = wn + np * 16 + brow;
                int slot = 2 * ks + bhalf;
                uint32_t bd = base + 2 * AB + (uint32_t)(r * 128 + ((slot ^ (r & 7)) << 4));
                ldsm4(bhf[np][0], bhf[np][1], bhf[np][2], bhf[np][3], bd);
                ldsm4(blf[np][0], blf[np][1], blf[np][2], blf[np][3], bd + BB);
            }
#pragma unroll
            for (int mt = 0; mt < 2; mt++)
#pragma unroll
                for (int nt = 0; nt < 4; nt++) {
                    int np = nt >> 1, sel = (nt & 1) * 2;
                    mma16816(acc[mt][nt], ahf[mt][0], ahf[mt][1], ahf[mt][2], ahf[mt][3],
                             bhf[np][sel], bhf[np][sel + 1]);
                }
#pragma unroll
            for (int mt = 0; mt < 2; mt++)
#pragma unroll
                for (int nt = 0; nt < 4; nt++) {
                    int np = nt >> 1, sel = (nt & 1) * 2;
                    mma16816(acc[mt][nt], ahf[mt][0], ahf[mt][1], ahf[mt][2], ahf[mt][3],
                             blf[np][sel], blf[np][sel + 1]);
                }
#pragma unroll
            for (int mt = 0; mt < 2; mt++)
#pragma unroll
                for (int nt = 0; nt < 4; nt++) {
                    int np = nt >> 1, sel = (nt & 1) * 2;
                    mma16816(acc[mt][nt], alf[mt][0], alf[mt][1], alf[mt][2], alf[mt][3],
                             bhf[np][sel], bhf[np][sel + 1]);
                }
        }
    }
#pragma unroll
    for (int mt = 0; mt < 2; mt++)
#pragma unroll
        for (int nt = 0; nt < 4; nt++) {
            int row = m0 + wm + mt * 16 + g;
            int col = n0 + wn + nt * 8 + tig * 2;
            float bv0 = bias ? bias[col] : 0.f;
            float bv1 = bias ? bias[col + 1] : 0.f;
            float2 v0 = make_float2(acc[mt][nt][0] + bv0, acc[mt][nt][1] + bv1);
            float2 v1 = make_float2(acc[mt][nt][2] + bv0, acc[mt][nt][3] + bv1);
            *(float2*)&C[(size_t)row * Ntot + col] = v0;
            *(float2*)&C[(size_t)(row + 8) * Ntot + col] = v1;
        }
}

// ---------------- fp32 GEMM for lin2 ----------------
template <int BM, int BN, int BK, int TM, int TN>
__global__ void k_gemm_bias(const float* __restrict__ A, const float* __restrict__ B,
                            const float* __restrict__ bias, float* __restrict__ C,
                            int M, int Nn, int K) {
    constexpr int THREADS = (BM / TM) * (BN / TN);
    __shared__ float As[BM][BK + 1];
    __shared__ float Bs[BK][BN + 1];
    int tid = threadIdx.x;
    int rm = tid / (BN / TN);
    int rn = tid % (BN / TN);
    int m0 = blockIdx.y * BM, n0 = blockIdx.x * BN;
    float acc[TM][TN];
#pragma unroll
    for (int m = 0; m < TM; m++)
#pragma unroll
        for (int n = 0; n < TN; n++) acc[m][n] = 0.f;

    for (int k0 = 0; k0 < K; k0 += BK) {
        for (int idx = tid; idx < BM * BK; idx += THREADS) {
            int r = idx / BK, c = idx % BK;
            As[r][c] = A[(size_t)(m0 + r) * K + k0 + c];
        }
        for (int idx = tid; idx < BK * BN; idx += THREADS) {
            int r = idx / BN, c = idx % BN;
            Bs[r][c] = B[(size_t)(k0 + r) * Nn + n0 + c];
        }
        __syncthreads();
#pragma unroll
        for (int kk = 0; kk < BK; kk++) {
            float a[TM], b[TN];
#pragma unroll
            for (int m = 0; m < TM; m++) a[m] = As[rm * TM + m][kk];
#pragma unroll
            for (int n = 0; n < TN; n++) b[n] = Bs[kk][rn * TN + n];
#pragma unroll
            for (int m = 0; m < TM; m++)
#pragma unroll
                for (int n = 0; n < TN; n++) acc[m][n] = fmaf(a[m], b[n], acc[m][n]);
        }
        __syncthreads();
    }
#pragma unroll
    for (int m = 0; m < TM; m++) {
        int row = m0 + rm * TM + m;
#pragma unroll
        for (int n = 0; n < TN; n++) {
            int col = n0 + rn * TN + n;
            float v = acc[m][n];
            if (bias) v += bias[col];
            C[(size_t)row * Nn + col] = v;
        }
    }
}

// ---------------- per-node scores: fp32 row-side exps + fp16 j-side exps ----------------
template <int F>
__global__ void k_attn_scores(const float* __restrict__ hfeat,
                              const float* __restrict__ a_src,
                              const float* __restrict__ a_dst,
                              float* __restrict__ sc,
                              __half* __restrict__ sch) {
    int n = blockIdx.x * (blockDim.x >> 5) + (threadIdx.x >> 5);
    int lane = threadIdx.x & 31;
    if (n >= NN) return;
    const float* row = hfeat + (size_t)n * (H * F);
#pragma unroll
    for (int h = 0; h < H; h++) {
        float ss = 0.f, sd = 0.f;
        for (int k = lane; k < F; k += 32) {
            float v = row[h * F + k];
            ss = fmaf(v, a_src[h * F + k], ss);
            sd = fmaf(v, a_dst[h * F + k], sd);
        }
#pragma unroll
        for (int o = 16; o; o >>= 1) {
            ss += __shfl_xor_sync(0xffffffffu, ss, o);
            sd += __shfl_xor_sync(0xffffffffu, sd, o);
        }
        if (lane == 0) {
            int idx = h * NN + n;
            sc[1 * HN + idx] = expf(ss);
            sc[2 * HN + idx] = expf(LRELU * ss);
            sch[idx]      = __float2half_rn(expf(sd));
            sch[HN + idx] = __float2half_rn(expf(LRELU * sd));
        }
    }
}

// ================ GAT aggregation: half2 weight-gen, fp16 MMA, ones-col denominator ================
template <int F>
__device__ __forceinline__ void load_chunk(int t, int head, int i0, int c, int buf,
                                           char* BtB, unsigned* mk, __half* edh,
                                           const __half* hTh, const __half* sch) {
    constexpr int BT = F * 128;
    char* dst = BtB + buf * BT;
    for (int idx = t; idx < F * 8; idx += 256) {
        int f = idx >> 3, q = idx & 7;
        uint32_t off = (uint32_t)(f * 128 + (((q ^ (f & 7)) << 4)));
        cp16(smem_u32(dst + off), hTh + (size_t)(head * F + f) * NN + c * 64 + q * 8);
    }
    if (t < 128) cp8(smem_u32(mk + buf * 256 + t * 2), &g_mask[(size_t)(i0 + t) * NW + c * 2]);
    if (t < 16) {
        int a = t >> 3, q = t & 7;   // a: 0=exp(ed), 1=exp(.2ed); q: 8 halves each
        cp16(smem_u32(edh + buf * 128 + a * 64 + q * 8),
             &sch[(size_t)a * HN + head * NN + c * 64 + q * 8]);
    }
}

template <int F>
__global__ __launch_bounds__(256) void k_gat_hmma(const __half* __restrict__ hTh,
                                                  const float* __restrict__ sc,
                                                  const __half* __restrict__ sch,
                                                  float* __restrict__ part,
                                                  float* __restrict__ dp) {
    constexpr int BT = F * 128;
    constexpr int MPF = F / 16;
    constexpr uint32_t ONES = 0x3C003C00u;
    extern __shared__ char smem[];
    char* BtB = smem;                               // [3][BT]
    unsigned* mk = (unsigned*)(smem + 3 * BT);      // [3][256]
    __half* edh = (__half*)(smem + 3 * BT + 3072);  // [3][128] halves

    int t = threadIdx.x, wid = t >> 5, lane = t & 31;
    int g = lane >> 2, tig = lane & 3;
    int head = blockIdx.y, i0 = blockIdx.x * 128;
    int z = blockIdx.z;
    int c0 = z * 32;
    uint32_t sb = smem_u32(smem);

    int r0 = wid * 16 + g, r1 = r0 + 8;
    const float* scb = sc + head * NN + i0;
    __half2 E0h = __float2half2_rn(scb[HN + r0]);
    __half2 e0h = __float2half2_rn(scb[2 * HN + r0]);
    __half2 E1h = __float2half2_rn(scb[HN + r1]);
    __half2 e1h = __float2half2_rn(scb[2 * HN + r1]);

    int flr = ((lane >> 4) & 1) * 8 + (lane & 7);
    int qb = (lane >> 3) & 1;
    int sxw = flr & 7;
    uint32_t fcol = (uint32_t)(flr * 128);

    float acc[2 * MPF][4];
#pragma unroll
    for (int nt = 0; nt < 2 * MPF; nt++)
#pragma unroll
        for (int q = 0; q < 4; q++) acc[nt][q] = 0.f;
    float accd[4] = {0.f, 0.f, 0.f, 0.f};

    load_chunk<F>(t, head, i0, c0, 0, BtB, mk, edh, hTh, sch);
    CP_COMMIT();
    load_chunk<F>(t, head, i0, c0 + 1, 1, BtB, mk, edh, hTh, sch);
    CP_COMMIT();

    for (int cc = 0; cc < 32; cc++) {
        int b = cc % 3;
        CP_WAIT1();
        __syncthreads();
        if (cc < 30)
            load_chunk<F>(t, head, i0, c0 + cc + 2, (cc + 2) % 3, BtB, mk, edh, hTh, sch);
        CP_COMMIT();
        unsigned* mkb = mk + b * 256;
        unsigned m0a = mkb[r0 * 2], m0b = mkb[r0 * 2 + 1];
        unsigned m1a = mkb[r1 * 2], m1b = mkb[r1 * 2 + 1];
        const __half2* eh = (const __half2*)(edh + b * 128);
        uint32_t bufbase = sb + (uint32_t)(b * BT);
#pragma unroll
        for (int ks = 0; ks < 4; ks++) {
            int jh = (ks * 16 + tig * 2) >> 1;      // half2 index of j-pair
            __half2 EvL = eh[jh];
            __half2 EvH = eh[jh + 4];
            __half2 e2L = eh[32 + jh];
            __half2 e2H = eh[32 + jh + 4];
            int bit = (ks & 1) * 16 + tig * 2;
            unsigned w0 = (ks < 2) ? m0a : m0b;
            unsigned w1 = (ks < 2) ? m1a : m1b;

            uint32_t A0 = wgen2(E0h, e0h, EvL, e2L, w0, bit);
            uint32_t A1 = wgen2(E1h, e1h, EvL, e2L, w1, bit);
            uint32_t A2 = wgen2(E0h, e0h, EvH, e2H, w0, bit + 8);
            uint32_t A3 = wgen2(E1h, e1h, EvH, e2H, w1, bit + 8);

            mma16816h(accd, A0, A1, A2, A3, ONES, ONES);

            uint32_t swz = (uint32_t)((((2 * ks + qb) ^ sxw) << 4));
#pragma unroll
            for (int mp = 0; mp < MPF; mp++) {
                uint32_t ad = bufbase + fcol + (uint32_t)(mp * 2048) + swz;
                uint32_t bh0, bh1, bh2, bh3;
                ldsm4(bh0, bh1, bh2, bh3, ad);
                mma16816h(acc[2 * mp],     A0, A1, A2, A3, bh0, bh1);
                mma16816h(acc[2 * mp + 1], A0, A1, A2, A3, bh2, bh3);
            }
        }
    }
    if (tig == 0) {
        dp[(size_t)z * HN + head * NN + i0 + r0] = accd[0];
        dp[(size_t)z * HN + head * NN + i0 + r1] = accd[2];
    }
    float* pz = part + (size_t)z * NN * (H * F);
#pragma unroll
    for (int nt = 0; nt < 2 * MPF; nt++) {
        int col = head * F + nt * 8 + tig * 2;
        *(float2*)&pz[(size_t)(i0 + r0) * (H * F) + col] = make_float2(acc[nt][0], acc[nt][1]);
        *(float2*)&pz[(size_t)(i0 + r1) * (H * F) + col] = make_float2(acc[nt][2], acc[nt][3]);
    }
}

// ---- combine K-split partials, normalize, optional bf16 split output ----
template <int F, bool SPLIT>
__global__ void k_gat_fin(const float* __restrict__ part, const float* __restrict__ dp,
                          float* __restrict__ out,
                          __nv_bfloat16* __restrict__ oh, __nv_bfloat16* __restrict__ ol) {
    constexpr int HF = H * F;
    int idx = blockIdx.x * blockDim.x + threadIdx.x;
    int e0 = idx * 4;
    int row = e0 / HF, cc = e0 % HF, head = cc / F;
    float inv = 1.f / (dp[head * NN + row] + dp[HN + head * NN + row]);
    float4 p0 = ((const float4*)part)[idx];
    float4 p1 = ((const float4*)(part + (size_t)NN * HF))[idx];
    float v0 = (p0.x + p1.x) * inv, v1 = (p0.y + p1.y) * inv;
    float v2 = (p0.z + p1.z) * inv, v3 = (p0.w + p1.w) * inv;
    if (SPLIT) {
        __nv_bfloat162 h0 = __floats2bfloat162_rn(v0, v1);
        __nv_bfloat162 h1 = __floats2bfloat162_rn(v2, v3);
        __nv_bfloat162 l0 = __floats2bfloat162_rn(v0 - __bfloat162float(h0.x),
                                                  v1 - __bfloat162float(h0.y));
        __nv_bfloat162 l1 = __floats2bfloat162_rn(v2 - __bfloat162float(h1.x),
                                                  v3 - __bfloat162float(h1.y));
        ((__nv_bfloat162*)oh)[idx * 2] = h0;
        ((__nv_bfloat162*)oh)[idx * 2 + 1] = h1;
        ((__nv_bfloat162*)ol)[idx * 2] = l0;
        ((__nv_bfloat162*)ol)[idx * 2 + 1] = l1;
    } else {
        ((float4*)out)[idx] = make_float4(v0, v1, v2, v3);
    }
}

// ---------------- batchnorm ----------------
template <int C>
__global__ void k_bn_part(const float* __restrict__ z, float* __restrict__ part) {
    constexpr int RL = 256 / C;
    int blk = blockIdx.x;
    int t = threadIdx.x;
    int col = t % C, rl = t / C;
    float s = 0.f, s2 = 0.f;
    for (int r = rl; r < 128; r += RL) {
        float v = z[(size_t)(blk * 128 + r) * C + col];
        s += v; s2 += v * v;
    }
    __shared__ float sh[256], sh2[256];
    sh[t] = s; sh2[t] = s2;
    __syncthreads();
    if (rl == 0) {
#pragma unroll
        for (int q = 1; q < RL; q++) { s += sh[q * C + col]; s2 += sh2[q * C + col]; }
        part[blk * 2 * C + col] = s;
        part[blk * 2 * C + C + col] = s2;
    }
}
template <int C>
__global__ void k_bn_fin(const float* __restrict__ part,
                         float* __restrict__ mean, float* __restrict__ rstd) {
    int c = threadIdx.x;
    if (c >= C) return;
    double s = 0.0, s2 = 0.0;
    for (int b = 0; b < 32; b++) { s += part[b * 2 * C + c]; s2 += part[b * 2 * C + C + c]; }
    double mu = s / NN;
    double var = s2 / NN - mu * mu;
    mean[c] = (float)mu;
    rstd[c] = rsqrtf((float)var + BN_EPS);
}

__global__ void k_bn_elu(const float* __restrict__ z, const float* __restrict__ mean,
                         const float* __restrict__ rstd, const float* __restrict__ gamma,
                         const float* __restrict__ beta, float* __restrict__ out, int C) {
    int idx = blockIdx.x * blockDim.x + threadIdx.x;
    int c = idx % C;
    float v = (z[idx] - mean[c]) * rstd[c] * gamma[c] + beta[c];
    out[idx] = v > 0.f ? v : (expf(v) - 1.f);
}

__global__ void k_bn_elu_split(const float* __restrict__ z, const float* __restrict__ mean,
                               const float* __restrict__ rstd, const float* __restrict__ gamma,
                               const float* __restrict__ beta,
                               __nv_bfloat16* __restrict__ oh, __nv_bfloat16* __restrict__ ol,
                               int C) {
    int idx = blockIdx.x * blockDim.x + threadIdx.x;
    int c = idx % C;
    float v = (z[idx] - mean[c]) * rstd[c] * gamma[c] + beta[c];
    v = v > 0.f ? v : (expf(v) - 1.f);
    __nv_bfloat16 hi = __float2bfloat16(v);
    oh[idx] = hi;
    ol[idx] = __float2bfloat16(v - __bfloat162float(hi));
}

// ---------------- launch ----------------
extern "C" void kernel_launch(void* const* d_in, const int* in_sizes, int n_in,
                              void* d_out, int out_size) {
    const float* x   = (const float*)d_in[0];
    const int*   adj = (const int*)d_in[1];
    const float* W1  = (const float*)d_in[2];
    const float* a1s = (const float*)d_in[3];
    const float* a1d = (const float*)d_in[4];
    const float* lw1 = (const float*)d_in[5];
    const float* lb1 = (const float*)d_in[6];
    const float* g1  = (const float*)d_in[7];
    const float* be1 = (const float*)d_in[8];
    const float* W2  = (const float*)d_in[9];
    const float* a2s = (const float*)d_in[10];
    const float* a2d = (const float*)d_in[11];
    const float* lw2 = (const float*)d_in[12];
    const float* lb2 = (const float*)d_in[13];
    const float* g2  = (const float*)d_in[14];
    const float* be2 = (const float*)d_in[15];
    float* out = (float*)d_out;

    float *h1, *x2, *h2, *x3, *z4, *sc1, *sc2, *mean, *rstd, *bnp, *part, *dp;
    __half *sch1, *sch2, *h1th, *h2th;
    __nv_bfloat16 *ah, *al, *wth, *wtl, *lw1th, *lw1tl, *w2th, *w2tl;
    cudaGetSymbolAddress((void**)&h1, g_h1);
    cudaGetSymbolAddress((void**)&x2, g_x2);
    cudaGetSymbolAddress((void**)&h2, g_h2);
    cudaGetSymbolAddress((void**)&x3, g_x3);
    cudaGetSymbolAddress((void**)&z4, g_z4);
    cudaGetSymbolAddress((void**)&sc1, g_sc1);
    cudaGetSymbolAddress((void**)&sc2, g_sc2);
    cudaGetSymbolAddress((void**)&sch1, g_sch1);
    cudaGetSymbolAddress((void**)&sch2, g_sch2);
    cudaGetSymbolAddress((void**)&mean, g_mean);
    cudaGetSymbolAddress((void**)&rstd, g_rstd);
    cudaGetSymbolAddress((void**)&bnp, g_bnpart);
    cudaGetSymbolAddress((void**)&part, g_part);
    cudaGetSymbolAddress((void**)&dp, g_dp);
    cudaGetSymbolAddress((void**)&h1th, g_h1th);
    cudaGetSymbolAddress((void**)&h2th, g_h2th);
    cudaGetSymbolAddress((void**)&ah, g_ah);
    cudaGetSymbolAddress((void**)&al, g_al);
    cudaGetSymbolAddress((void**)&wth, g_wth);
    cudaGetSymbolAddress((void**)&wtl, g_wtl);
    cudaGetSymbolAddress((void**)&lw1th, g_lw1th);
    cudaGetSymbolAddress((void**)&lw1tl, g_lw1tl);
    cudaGetSymbolAddress((void**)&w2th, g_w2th);
    cudaGetSymbolAddress((void**)&w2tl, g_w2tl);

    const int SMEM1 = 3 * F1 * 128 + 3072 + 768;   // ~52.9 KB
    const int SMEM2 = 3 * F2 * 128 + 3072 + 768;   // ~16.1 KB
    const int SMEMG128 = 3 * (2 * 16384 + 2 * 128 * 128);
    const int SMEMG64  = 3 * (2 * 16384 + 2 * 64 * 128);
    cudaFuncSetAttribute((const void*)k_gat_hmma<F1>,
                         cudaFuncAttributeMaxDynamicSharedMemorySize, SMEM1);
    cudaFuncSetAttribute((const void*)k_gat_hmma<F2>,
                         cudaFuncAttributeMaxDynamicSharedMemorySize, SMEM2);
    cudaFuncSetAttribute((const void*)k_gemm_hmma<128, 16>,
                         cudaFuncAttributeMaxDynamicSharedMemorySize, SMEMG128);
    cudaFuncSetAttribute((const void*)k_gemm_hmma<64, 8>,
                         cudaFuncAttributeMaxDynamicSharedMemorySize, SMEMG64);

    static cudaStream_t s2 = nullptr;
    static cudaEvent_t e0 = nullptr, e2 = nullptr, e3 = nullptr, e4 = nullptr, e5 = nullptr;
    if (!s2) {
        cudaStreamCreateWithFlags(&s2, cudaStreamNonBlocking);
        cudaEventCreateWithFlags(&e0, cudaEventDisableTiming);
        cudaEventCreateWithFlags(&e2, cudaEventDisableTiming);
        cudaEventCreateWithFlags(&e3, cudaEventDisableTiming);
        cudaEventCreateWithFlags(&e4, cudaEventDisableTiming);
        cudaEventCreateWithFlags(&e5, cudaEventDisableTiming);
    }

    cudaEventRecord(e0, 0);
    cudaStreamWaitEvent(s2, e0, 0);
    k_pack_mask<<<(NN * NN) / 256, 256, 0, s2>>>(adj);
    k_transpose_split<<<dim3(512 / 32, HID1 / 32), dim3(32, 8), 0, s2>>>(lw1, lw1th, lw1tl, 512, HID1);
    k_transpose_split<<<dim3(HID1 / 32, 128 / 32), dim3(32, 8), 0, s2>>>(W2, w2th, w2tl, HID1, 128);

    k_split_bf16<<<(NN * IN_F / 4) / 256, 256>>>(x, ah, al);
    k_transpose_split<<<dim3(IN_F / 32, 512 / 32), dim3(32, 8)>>>(W1, wth, wtl, IN_F, 512);
    k_gemm_hmma<128, 16><<<dim3(NN / 128, 512 / 128), 512, SMEMG128>>>(
        ah, al, wth, wtl, nullptr, h1, IN_F, 512);

    cudaEventRecord(e2, 0);
    cudaStreamWaitEvent(s2, e2, 0);
    k_transpose_f16<<<dim3(NN / 32, 512 / 32), dim3(32, 8), 0, s2>>>(h1, h1th, NN, 512);
    k_attn_scores<F1><<<NN / 8, 256>>>(h1, a1s, a1d, sc1, sch1);
    cudaEventRecord(e3, s2);
    cudaStreamWaitEvent(0, e3, 0);

    k_gat_hmma<F1><<<dim3(NN / 128, H, 2), 256, SMEM1>>>(h1th, sc1, sch1, part, dp);
    k_gat_fin<F1, true><<<(NN * 512 / 4) / 256, 256>>>(part, dp, nullptr, ah, al);

    k_gemm_hmma<64, 8><<<dim3(NN / 128, HID1 / 64), 256, SMEMG64>>>(
        ah, al, lw1th, lw1tl, lb1, x2, 512, HID1);

    k_bn_part<HID1><<<32, 256>>>(x2, bnp);
    k_bn_fin<HID1><<<1, 64>>>(bnp, mean, rstd);
    k_bn_elu_split<<<(NN * HID1) / 256, 256>>>(x2, mean, rstd, g1, be1, ah, al, HID1);

    k_gemm_hmma<128, 16><<<dim3(NN / 128, 1), 512, SMEMG128>>>(
        ah, al, w2th, w2tl, nullptr, h2, HID1, 128);

    cudaEventRecord(e4, 0);
    cudaStreamWaitEvent(s2, e4, 0);
    k_transpose_f16<<<dim3(NN / 32, 128 / 32), dim3(32, 8), 0, s2>>>(h2, h2th, NN, 128);
    k_attn_scores<F2><<<NN / 8, 256>>>(h2, a2s, a2d, sc2, sch2);
    cudaEventRecord(e5, s2);
    cudaStreamWaitEvent(0, e5, 0);

    k_gat_hmma<F2><<<dim3(NN / 128, H, 2), 256, SMEM2>>>(h2th, sc2, sch2, part, dp);
    k_gat_fin<F2, false><<<(NN * 128 / 4) / 256, 256>>>(part, dp, x3, nullptr, nullptr);

    k_gemm_bias<128, 16, 32, 4, 2><<<dim3(1, NN / 128), 256>>>(x3, lw2, lb2, z4, NN, OUT_F, 128);

    k_bn_part<OUT_F><<<32, 256>>>(z4, bnp);
    k_bn_fin<OUT_F><<<1, 64>>>(bnp, mean, rstd);
    k_bn_elu<<<(NN * OUT_F) / 256, 256>>>(z4, mean, rstd, g2, be2, out, OUT_F);
}